// round 4
// baseline (speedup 1.0000x reference)
#include <cuda_runtime.h>
#include <cuda_bf16.h>
#include <cstdint>

// ============================================================================
// LIIF sampler via mma.sync bf16 3-pass split. Round 4: 64-point CTAs,
// 2 CTAs/SM (launch_bounds(256,2)), single-plane W streaming (hi/lo planes as
// separate 16.9KB chunks), flattened 54-plane prefetch pipeline across layers.
// ============================================================================

#define HQv 384
#define WQv 384
#define HFv 48
#define WFv 48

#define MT  64
#define NTH 256

// smem layout (bytes)
#define A_HI_OFF 0
#define A_LO_OFF 33792                    // 64*528
#define WBUF_OFF 67584
#define WPLANE   16896                    // 32 rows * 528
#define BIAS_OFF (WBUF_OFF + 2 * WPLANE)  // 101376
#define W4_OFF   (BIAS_OFF + 4096)        // 105472
#define B4_OFF   (W4_OFF + 3072)          // 108544
#define OACC_OFF (B4_OFF + 16)            // 108560
#define SMEM_TOTAL (OACC_OFF + 768 + 16)  // 109344

// weight blob: per layer, hi plane [kpad][256] bf16 then lo plane.
__device__ __align__(128) unsigned char g_wblob[884736];
__constant__ int c_lbase[4] = {0, 98304, 360448, 622592};

// ---------------------------------------------------------------------------
__device__ __forceinline__ uint32_t smem_u32(const void* p) {
    uint32_t a;
    asm("{ .reg .u64 t; cvta.to.shared.u64 t, %1; cvt.u32.u64 %0, t; }"
        : "=r"(a) : "l"(p));
    return a;
}
__device__ __forceinline__ void ldsm4(uint32_t* r, uint32_t a) {
    asm volatile("ldmatrix.sync.aligned.m8n8.x4.shared.b16 {%0,%1,%2,%3}, [%4];"
                 : "=r"(r[0]), "=r"(r[1]), "=r"(r[2]), "=r"(r[3]) : "r"(a));
}
__device__ __forceinline__ void ldsm4t(uint32_t& r0, uint32_t& r1, uint32_t& r2,
                                       uint32_t& r3, uint32_t a) {
    asm volatile("ldmatrix.sync.aligned.m8n8.x4.trans.shared.b16 {%0,%1,%2,%3}, [%4];"
                 : "=r"(r0), "=r"(r1), "=r"(r2), "=r"(r3) : "r"(a));
}
__device__ __forceinline__ void mma16816(float* d, const uint32_t* a,
                                         uint32_t b0, uint32_t b1) {
    asm volatile(
        "mma.sync.aligned.m16n8k16.row.col.f32.bf16.bf16.f32 "
        "{%0,%1,%2,%3}, {%4,%5,%6,%7}, {%8,%9}, {%0,%1,%2,%3};"
        : "+f"(d[0]), "+f"(d[1]), "+f"(d[2]), "+f"(d[3])
        : "r"(a[0]), "r"(a[1]), "r"(a[2]), "r"(a[3]), "r"(b0), "r"(b1));
}
__device__ __forceinline__ void cpasync16(uint32_t dst, const void* src) {
    asm volatile("cp.async.cg.shared.global [%0], [%1], 16;"
                 :: "r"(dst), "l"(src) : "memory");
}
__device__ __forceinline__ void cp_commit() {
    asm volatile("cp.async.commit_group;" ::: "memory");
}
__device__ __forceinline__ void cvt2(float a, float b, uint32_t& hi, uint32_t& lo) {
    __nv_bfloat16 ah = __float2bfloat16(a), bh = __float2bfloat16(b);
    __nv_bfloat16 al = __float2bfloat16(a - __bfloat162float(ah));
    __nv_bfloat16 bl = __float2bfloat16(b - __bfloat162float(bh));
    hi = (uint32_t)__bfloat16_as_ushort(ah) | ((uint32_t)__bfloat16_as_ushort(bh) << 16);
    lo = (uint32_t)__bfloat16_as_ushort(al) | ((uint32_t)__bfloat16_as_ushort(bl) << 16);
}

// plane index (0..53) -> gmem pointer of a contiguous 16384B plane-chunk
__device__ __forceinline__ const unsigned char* plane_ptr(int g) {
    const int layer = (g < 6) ? 0 : (g < 22) ? 1 : (g < 38) ? 2 : 3;
    const int st = (layer == 0) ? 0 : (6 + 16 * (layer - 1));
    const int i = g - st;
    const int kc = i >> 1, sel = i & 1;
    const int kpad = layer ? 256 : 96;
    return g_wblob + c_lbase[layer] + (sel ? kpad * 512 : 0) + kc * 16384;
}
__device__ __forceinline__ void issue_plane(uint32_t sb, int tid,
                                            const unsigned char* src, int bsel) {
#pragma unroll
    for (int it = 0; it < 4; it++) {
        const int i = tid + it * 256;       // 0..1023
        const int r = i >> 5, s = i & 31;
        cpasync16(sb + WBUF_OFF + bsel * WPLANE + r * 528 + s * 16, src + i * 16);
    }
    cp_commit();
}

// ---------------------------------------------------------------------------
// Prep: split W0..W3 fp32 -> bf16 hi/lo planes in g_wblob.
// ---------------------------------------------------------------------------
__global__ void liif_prep_kernel(const float* __restrict__ W0, const float* __restrict__ W1,
                                 const float* __restrict__ W2, const float* __restrict__ W3)
{
    const int row = blockIdx.x;       // 0..863
    const int n = threadIdx.x;
    int layer, k;
    if (row < 96) { layer = 0; k = row; }
    else { layer = 1 + (row - 96) / 256; k = (row - 96) & 255; }
    const float* W = (layer == 0) ? W0 : (layer == 1) ? W1 : (layer == 2) ? W2 : W3;
    const int Kl = (layer == 0) ? 71 : 256;
    const int kpad = (layer == 0) ? 96 : 256;
    const float val = (k < Kl) ? W[k * 256 + n] : 0.0f;
    __nv_bfloat16 hi = __float2bfloat16(val);
    __nv_bfloat16 lo = __float2bfloat16(val - __bfloat162float(hi));
    unsigned char* base = g_wblob + c_lbase[layer];
    *(unsigned short*)(base + (size_t)k * 512 + n * 2) = __bfloat16_as_ushort(hi);
    *(unsigned short*)(base + (size_t)kpad * 512 + (size_t)k * 512 + n * 2) =
        __bfloat16_as_ushort(lo);
}

// ---------------------------------------------------------------------------
__global__ __launch_bounds__(NTH, 2)
void liif_hmma_kernel(
    const float* __restrict__ x, const float* __restrict__ coord,
    const float* __restrict__ cell, const float* __restrict__ lr,
    const float* __restrict__ b0, const float* __restrict__ b1,
    const float* __restrict__ b2, const float* __restrict__ b3,
    const float* __restrict__ W4, const float* __restrict__ b4,
    float* __restrict__ out)
{
    extern __shared__ __align__(16) char smem[];
    const uint32_t sb = smem_u32(smem);
    const int tid = threadIdx.x;
    const int lane = tid & 31;
    const int wid = tid >> 5;
    const int wm = wid & 1;   // 2 warps along M (32 rows each)
    const int wn = wid >> 1;  // 4 warps along N (64 cols each)

    float* bias_s = (float*)(smem + BIAS_OFF);
    float* w4_s   = (float*)(smem + W4_OFF);
    float* b4_s   = (float*)(smem + B4_OFF);
    float* oacc   = (float*)(smem + OACC_OFF);

    // prefetch first W plane immediately (lands during gather)
    issue_plane(sb, tid, plane_ptr(0), 0);

    // stage biases + W4
    bias_s[tid] = b0[tid]; bias_s[256 + tid] = b1[tid];
    bias_s[512 + tid] = b2[tid]; bias_s[768 + tid] = b3[tid];
    for (int i = tid; i < 768; i += NTH) w4_s[i] = W4[i];
    if (tid < 3) b4_s[tid] = b4[tid];

    // ---- gather -> A0 (bf16 hi/lo, rows=64 points, stride 528B) ----
    const int p  = tid & 63;
    const int q  = tid >> 6;   // 4 channel groups per point
    const int gp = blockIdx.x * MT + p;
    const int b  = gp / (HQv * WQv);
    const int rem = gp % (HQv * WQv);
    const int yq = rem / WQv, xq = rem % WQv;
    const float gy = coord[((size_t)(b * HQv + yq) * WQv + xq) * 2 + 0];
    const float gx = coord[((size_t)(b * HQv + yq) * WQv + xq) * 2 + 1];

    float tx = __fmul_rn(__fadd_rn(__fmul_rn(__fadd_rn(gx, 1.0f), (float)WFv), -1.0f), 0.5f);
    float ty = __fmul_rn(__fadd_rn(__fmul_rn(__fadd_rn(gy, 1.0f), (float)HFv), -1.0f), 0.5f);
    const int ixn = (int)rintf(tx);
    const int iyn = (int)rintf(ty);
    const bool valid = (ixn >= 0) && (ixn < WFv) && (iyn >= 0) && (iyn < HFv);
    const int ixc = min(max(ixn, 0), WFv - 1);
    const int iyc = min(max(iyn, 0), HFv - 1);

    {   // channels q*16 .. q*16+15 -> u32 slots q*8..q*8+7 of row p
        const float* xb = x + (size_t)b * 64 * (HFv * WFv) + (size_t)iyc * WFv + ixc;
        char* rh = smem + A_HI_OFF + (size_t)p * 528 + q * 32;
        char* rl = smem + A_LO_OFF + (size_t)p * 528 + q * 32;
#pragma unroll
        for (int j = 0; j < 8; j++) {
            const int c0 = q * 16 + 2 * j;
            const float f0 = valid ? xb[(size_t)c0 * (HFv * WFv)] : 0.0f;
            const float f1 = valid ? xb[(size_t)(c0 + 1) * (HFv * WFv)] : 0.0f;
            uint32_t hi, lo;
            cvt2(f0, f1, hi, lo);
            *(uint32_t*)(rh + j * 4) = hi;
            *(uint32_t*)(rl + j * 4) = lo;
        }
    }
    if (tid < 64) {  // scalar features -> cols 64..95 (u32 slots 32..47)
        float qy = 0.0f, qx = 0.0f;
        if (valid) {
            qy = __fadd_rn(__fdiv_rn(__fadd_rn(__fmul_rn(2.0f, (float)iyc), 1.0f), (float)HFv), -1.0f);
            qx = __fadd_rn(__fdiv_rn(__fadd_rn(__fmul_rn(2.0f, (float)ixc), 1.0f), (float)WFv), -1.0f);
        }
        float vals[32];
#pragma unroll
        for (int i = 0; i < 32; i++) vals[i] = 0.0f;
        vals[0] = __fmul_rn(__fadd_rn(gy, -qy), (float)HFv);
        vals[1] = __fmul_rn(__fadd_rn(gx, -qx), (float)WFv);
        vals[2] = __fmul_rn(cell[b * 2 + 0], (float)HFv);
        vals[3] = __fmul_rn(cell[b * 2 + 1], (float)WFv);
        const float rx = 1.0f / (float)HFv, ry = 1.0f / (float)WFv;
        const float lo_c = -1.0f + 1e-6f, hi_c = 1.0f - 1e-6f;
        float s[3][4];
        int j = 0;
#pragma unroll
        for (int a = 0; a < 2; a++) {
#pragma unroll
            for (int c2 = 0; c2 < 2; c2++) {
                const float vx = a ? 1.0f : -1.0f;
                const float vy = c2 ? 1.0f : -1.0f;
                float cy = __fadd_rn(__fadd_rn(gy, __fmul_rn(vx, rx)), 1e-6f);
                float cx = __fadd_rn(__fadd_rn(gx, __fmul_rn(vy, ry)), 1e-6f);
                cy = fminf(fmaxf(cy, lo_c), hi_c);
                cx = fminf(fmaxf(cx, lo_c), hi_c);
                float fx = __fmul_rn(__fadd_rn(__fmul_rn(__fadd_rn(cx, 1.0f), (float)WFv), -1.0f), 0.5f);
                float fy = __fmul_rn(__fadd_rn(__fmul_rn(__fadd_rn(cy, 1.0f), (float)HFv), -1.0f), 0.5f);
                int jx = min(max((int)rintf(fx), 0), WFv - 1);
                int jy = min(max((int)rintf(fy), 0), HFv - 1);
#pragma unroll
                for (int ch = 0; ch < 3; ch++)
                    s[ch][j] = lr[((size_t)(b * 3 + ch) * HFv + jy) * WFv + jx];
                j++;
            }
        }
#pragma unroll
        for (int ch = 0; ch < 3; ch++) {
            const float m = 0.25f * (s[ch][0] + s[ch][1] + s[ch][2] + s[ch][3]);
            float v = 0.0f;
#pragma unroll
            for (int qq = 0; qq < 4; qq++) { const float d = s[ch][qq] - m; v += d * d; }
            vals[4 + ch] = sqrtf(v * (1.0f / 3.0f));
        }
        char* rh = smem + A_HI_OFF + (size_t)p * 528 + 128;
        char* rl = smem + A_LO_OFF + (size_t)p * 528 + 128;
#pragma unroll
        for (int k = 0; k < 16; k++) {
            uint32_t hi, lo;
            cvt2(vals[2 * k], vals[2 * k + 1], hi, lo);
            *(uint32_t*)(rh + k * 4) = hi;
            *(uint32_t*)(rl + k * 4) = lo;
        }
    }

    // ---- 4 layers, flattened 54-plane pipeline ----
    float acc[2][8][4];
    const uint32_t aRowByte = (uint32_t)(wm * 32 + (lane & 15)) * 528 + (lane >> 4) * 16;
    const uint32_t bColByte = (uint32_t)(wn * 64 + (lane >> 4) * 8) * 2;
    const uint32_t bRowByte = (uint32_t)(lane & 15) * 528;

    int g = 0;  // global plane index
#pragma unroll 1
    for (int layer = 0; layer < 4; layer++) {
        const int np = (layer == 0) ? 6 : 16;
#pragma unroll
        for (int mt = 0; mt < 2; mt++)
#pragma unroll
            for (int nt = 0; nt < 8; nt++)
#pragma unroll
                for (int e = 0; e < 4; e++) acc[mt][nt][e] = 0.0f;

#pragma unroll 1
        for (int i = 0; i < np; i++, g++) {
            if (g + 1 < 54) {
                issue_plane(sb, tid, plane_ptr(g + 1), (g + 1) & 1);
                asm volatile("cp.async.wait_group 1;" ::: "memory");
            } else {
                asm volatile("cp.async.wait_group 0;" ::: "memory");
            }
            __syncthreads();

            const int kc = i >> 1;
            const int sel = i & 1;     // 0 = hi plane (2 passes), 1 = lo plane (1 pass)
            const uint32_t wb = sb + WBUF_OFF + (g & 1) * WPLANE;
#pragma unroll
            for (int kk = 0; kk < 2; kk++) {
                const uint32_t kByte = (uint32_t)(kc * 64 + kk * 32);
                uint32_t ah[2][4], al[2][4];
#pragma unroll
                for (int mt = 0; mt < 2; mt++) {
                    const uint32_t aoff = aRowByte + (uint32_t)(mt * 16) * 528 + kByte;
                    ldsm4(ah[mt], sb + A_HI_OFF + aoff);
                    if (sel == 0) ldsm4(al[mt], sb + A_LO_OFF + aoff);
                }
#pragma unroll
                for (int ng = 0; ng < 4; ng++) {
                    const uint32_t bo = bRowByte + (uint32_t)(kk * 16) * 528
                                      + bColByte + (uint32_t)(ng * 16) * 2;
                    uint32_t w0, w1, w2, w3;
                    ldsm4t(w0, w1, w2, w3, wb + bo);
#pragma unroll
                    for (int mt = 0; mt < 2; mt++) {
                        mma16816(acc[mt][2 * ng],     ah[mt], w0, w1);
                        mma16816(acc[mt][2 * ng + 1], ah[mt], w2, w3);
                        if (sel == 0) {
                            mma16816(acc[mt][2 * ng],     al[mt], w0, w1);
                            mma16816(acc[mt][2 * ng + 1], al[mt], w2, w3);
                        }
                    }
                }
            }
            __syncthreads();
        }

        const float* bl_bias = bias_s + layer * 256;
        if (layer < 3) {
            // epilogue: relu(D+b) -> bf16 hi/lo back into A (in place)
#pragma unroll
            for (int mt = 0; mt < 2; mt++) {
#pragma unroll
                for (int nt = 0; nt < 8; nt++) {
                    const int r0 = wm * 32 + mt * 16 + (lane >> 2);
                    const int c0 = wn * 64 + nt * 8 + (lane & 3) * 2;
                    const float bb0 = bl_bias[c0], bb1 = bl_bias[c0 + 1];
                    const float h00 = fmaxf(acc[mt][nt][0] + bb0, 0.0f);
                    const float h01 = fmaxf(acc[mt][nt][1] + bb1, 0.0f);
                    const float h10 = fmaxf(acc[mt][nt][2] + bb0, 0.0f);
                    const float h11 = fmaxf(acc[mt][nt][3] + bb1, 0.0f);
                    uint32_t hi, lo;
                    cvt2(h00, h01, hi, lo);
                    *(uint32_t*)(smem + A_HI_OFF + (size_t)r0 * 528 + c0 * 2) = hi;
                    *(uint32_t*)(smem + A_LO_OFF + (size_t)r0 * 528 + c0 * 2) = lo;
                    cvt2(h10, h11, hi, lo);
                    *(uint32_t*)(smem + A_HI_OFF + (size_t)(r0 + 8) * 528 + c0 * 2) = hi;
                    *(uint32_t*)(smem + A_LO_OFF + (size_t)(r0 + 8) * 528 + c0 * 2) = lo;
                }
            }
            // visibility ensured by next layer's first-plane __syncthreads
        } else {
            // final: out = relu(D + b3) @ W4 + b4 (exact fp32)
            if (tid < 192) oacc[tid] = 0.0f;
            __syncthreads();
            float sres[4][3];
#pragma unroll
            for (int ii = 0; ii < 4; ii++)
#pragma unroll
                for (int o = 0; o < 3; o++) sres[ii][o] = 0.0f;
#pragma unroll
            for (int nt = 0; nt < 8; nt++) {
#pragma unroll
                for (int e = 0; e < 2; e++) {
                    const int col = wn * 64 + nt * 8 + (lane & 3) * 2 + e;
                    const float bb = bl_bias[col];
                    const float w40 = w4_s[col * 3 + 0];
                    const float w41 = w4_s[col * 3 + 1];
                    const float w42 = w4_s[col * 3 + 2];
                    const float h0 = fmaxf(acc[0][nt][e] + bb, 0.0f);
                    const float h1 = fmaxf(acc[0][nt][2 + e] + bb, 0.0f);
                    const float h2 = fmaxf(acc[1][nt][e] + bb, 0.0f);
                    const float h3 = fmaxf(acc[1][nt][2 + e] + bb, 0.0f);
                    sres[0][0] = fmaf(h0, w40, sres[0][0]); sres[0][1] = fmaf(h0, w41, sres[0][1]); sres[0][2] = fmaf(h0, w42, sres[0][2]);
                    sres[1][0] = fmaf(h1, w40, sres[1][0]); sres[1][1] = fmaf(h1, w41, sres[1][1]); sres[1][2] = fmaf(h1, w42, sres[1][2]);
                    sres[2][0] = fmaf(h2, w40, sres[2][0]); sres[2][1] = fmaf(h2, w41, sres[2][1]); sres[2][2] = fmaf(h2, w42, sres[2][2]);
                    sres[3][0] = fmaf(h3, w40, sres[3][0]); sres[3][1] = fmaf(h3, w41, sres[3][1]); sres[3][2] = fmaf(h3, w42, sres[3][2]);
                }
            }
            const int rbase = wm * 32 + (lane >> 2);
#pragma unroll
            for (int ii = 0; ii < 4; ii++) {
                const int row = rbase + ((ii & 1) ? 8 : 0) + ((ii & 2) ? 16 : 0);
                const int sidx = (ii & 1) + ((ii & 2) ? 2 : 0);
#pragma unroll
                for (int o = 0; o < 3; o++)
                    atomicAdd(&oacc[row * 3 + o], sres[sidx][o]);
            }
            __syncthreads();
            if (tid < 64) {
                const size_t base = (size_t)(b * 3) * (HQv * WQv) + (size_t)yq * WQv + xq;
                out[base]                           = oacc[tid * 3 + 0] + b4_s[0];
                out[base + (size_t)(HQv * WQv)]     = oacc[tid * 3 + 1] + b4_s[1];
                out[base + (size_t)(2 * HQv * WQv)] = oacc[tid * 3 + 2] + b4_s[2];
            }
        }
    }
}

// ---------------------------------------------------------------------------
extern "C" void kernel_launch(void* const* d_in, const int* in_sizes, int n_in,
                              void* d_out, int out_size)
{
    const float* x     = (const float*)d_in[0];
    const float* coord = (const float*)d_in[1];
    const float* cell  = (const float*)d_in[2];
    const float* lr    = (const float*)d_in[3];
    const float* W0    = (const float*)d_in[4];
    const float* b0    = (const float*)d_in[5];
    const float* W1    = (const float*)d_in[6];
    const float* b1    = (const float*)d_in[7];
    const float* W2    = (const float*)d_in[8];
    const float* b2    = (const float*)d_in[9];
    const float* W3    = (const float*)d_in[10];
    const float* b3    = (const float*)d_in[11];
    const float* W4    = (const float*)d_in[12];
    const float* b4    = (const float*)d_in[13];
    float* out = (float*)d_out;

    liif_prep_kernel<<<864, 256>>>(W0, W1, W2, W3);

    const int P = out_size / 3;      // 589824
    const int nblk = P / MT;         // 9216

    cudaFuncSetAttribute(liif_hmma_kernel,
                         cudaFuncAttributeMaxDynamicSharedMemorySize, SMEM_TOTAL);
    liif_hmma_kernel<<<nblk, NTH, SMEM_TOTAL>>>(
        x, coord, cell, lr, b0, b1, b2, b3, W4, b4, out);
}

// round 5
// speedup vs baseline: 1.0723x; 1.0723x over previous
#include <cuda_runtime.h>
#include <cuda_bf16.h>
#include <cstdint>

// ============================================================================
// LIIF sampler via mma.sync bf16 3-pass split. Round 5: back to 128-pt CTAs
// (R3 structure, proven 2415us) but with 512 threads / 16 warps: warp grid
// 4Mx4N -> 64 acc/thread (no spill), 4 warps/SMSP to hide serial phases.
// ============================================================================

#define HQv 384
#define WQv 384
#define HFv 48
#define WFv 48

#define MT  128
#define NTH 512

// smem layout (bytes)
#define A_HI_OFF 0
#define A_LO_OFF (128 * 528)                 // 67584
#define WBUF_OFF (2 * 128 * 528)             // 135168
#define WPLANE   (32 * 528)                  // 16896
#define WBUF_SZ  (2 * WPLANE)                // 33792 (hi+lo)
#define BIAS_OFF (WBUF_OFF + 2 * WBUF_SZ)    // 202752
#define W4_OFF   (BIAS_OFF + 4096)           // 206848
#define B4_OFF   (W4_OFF + 3072)             // 209920
#define OACC_OFF (B4_OFF + 16)               // 209936
#define SMEM_TOTAL (OACC_OFF + 1536)         // 211472

// weight blob: per layer, hi plane [kpad][256] bf16 then lo plane.
__device__ __align__(128) unsigned char g_wblob[884736];
__constant__ int c_lbase[4] = {0, 98304, 360448, 622592};

// ---------------------------------------------------------------------------
__device__ __forceinline__ uint32_t smem_u32(const void* p) {
    uint32_t a;
    asm("{ .reg .u64 t; cvta.to.shared.u64 t, %1; cvt.u32.u64 %0, t; }"
        : "=r"(a) : "l"(p));
    return a;
}
__device__ __forceinline__ void ldsm4(uint32_t* r, uint32_t a) {
    asm volatile("ldmatrix.sync.aligned.m8n8.x4.shared.b16 {%0,%1,%2,%3}, [%4];"
                 : "=r"(r[0]), "=r"(r[1]), "=r"(r[2]), "=r"(r[3]) : "r"(a));
}
__device__ __forceinline__ void ldsm4t(uint32_t& r0, uint32_t& r1, uint32_t& r2,
                                       uint32_t& r3, uint32_t a) {
    asm volatile("ldmatrix.sync.aligned.m8n8.x4.trans.shared.b16 {%0,%1,%2,%3}, [%4];"
                 : "=r"(r0), "=r"(r1), "=r"(r2), "=r"(r3) : "r"(a));
}
__device__ __forceinline__ void mma16816(float* d, const uint32_t* a,
                                         uint32_t b0, uint32_t b1) {
    asm volatile(
        "mma.sync.aligned.m16n8k16.row.col.f32.bf16.bf16.f32 "
        "{%0,%1,%2,%3}, {%4,%5,%6,%7}, {%8,%9}, {%0,%1,%2,%3};"
        : "+f"(d[0]), "+f"(d[1]), "+f"(d[2]), "+f"(d[3])
        : "r"(a[0]), "r"(a[1]), "r"(a[2]), "r"(a[3]), "r"(b0), "r"(b1));
}
__device__ __forceinline__ void cpasync16(uint32_t dst, const void* src) {
    asm volatile("cp.async.cg.shared.global [%0], [%1], 16;"
                 :: "r"(dst), "l"(src) : "memory");
}
__device__ __forceinline__ void cp_commit() {
    asm volatile("cp.async.commit_group;" ::: "memory");
}
__device__ __forceinline__ void cvt2(float a, float b, uint32_t& hi, uint32_t& lo) {
    __nv_bfloat16 ah = __float2bfloat16(a), bh = __float2bfloat16(b);
    __nv_bfloat16 al = __float2bfloat16(a - __bfloat162float(ah));
    __nv_bfloat16 bl = __float2bfloat16(b - __bfloat162float(bh));
    hi = (uint32_t)__bfloat16_as_ushort(ah) | ((uint32_t)__bfloat16_as_ushort(bh) << 16);
    lo = (uint32_t)__bfloat16_as_ushort(al) | ((uint32_t)__bfloat16_as_ushort(bl) << 16);
}

// stage one K=32 chunk (hi plane + lo plane) into wbuf[bsel]
__device__ __forceinline__ void issue_chunk(uint32_t sb, int tid,
                                            const unsigned char* lbase, int kpad,
                                            int c, int bsel)
{
    // 2 planes x 32 rows x 32 segs of 16B = 2048 segs, 4 per thread at 512 thr
#pragma unroll
    for (int it = 0; it < 4; it++) {
        const int i = tid + it * NTH;
        const int pl = i >> 10;
        const int r = (i >> 5) & 31;
        const int s = i & 31;
        const unsigned char* src = lbase + (size_t)pl * ((size_t)kpad * 512)
                                 + (size_t)(c * 32 + r) * 512 + s * 16;
        const uint32_t dst = sb + WBUF_OFF + bsel * WBUF_SZ + pl * WPLANE + r * 528 + s * 16;
        cpasync16(dst, src);
    }
    cp_commit();
}

// ---------------------------------------------------------------------------
// Prep: split W0..W3 fp32 -> bf16 hi/lo planes in g_wblob.
// ---------------------------------------------------------------------------
__global__ void liif_prep_kernel(const float* __restrict__ W0, const float* __restrict__ W1,
                                 const float* __restrict__ W2, const float* __restrict__ W3)
{
    const int row = blockIdx.x;       // 0..863
    const int n = threadIdx.x;
    int layer, k;
    if (row < 96) { layer = 0; k = row; }
    else { layer = 1 + (row - 96) / 256; k = (row - 96) & 255; }
    const float* W = (layer == 0) ? W0 : (layer == 1) ? W1 : (layer == 2) ? W2 : W3;
    const int Kl = (layer == 0) ? 71 : 256;
    const int kpad = (layer == 0) ? 96 : 256;
    const float val = (k < Kl) ? W[k * 256 + n] : 0.0f;
    __nv_bfloat16 hi = __float2bfloat16(val);
    __nv_bfloat16 lo = __float2bfloat16(val - __bfloat162float(hi));
    unsigned char* base = g_wblob + c_lbase[layer];
    *(unsigned short*)(base + (size_t)k * 512 + n * 2) = __bfloat16_as_ushort(hi);
    *(unsigned short*)(base + (size_t)kpad * 512 + (size_t)k * 512 + n * 2) =
        __bfloat16_as_ushort(lo);
}

// ---------------------------------------------------------------------------
__global__ __launch_bounds__(NTH, 1)
void liif_hmma_kernel(
    const float* __restrict__ x, const float* __restrict__ coord,
    const float* __restrict__ cell, const float* __restrict__ lr,
    const float* __restrict__ b0, const float* __restrict__ b1,
    const float* __restrict__ b2, const float* __restrict__ b3,
    const float* __restrict__ W4, const float* __restrict__ b4,
    float* __restrict__ out)
{
    extern __shared__ __align__(16) char smem[];
    const uint32_t sb = smem_u32(smem);
    const int tid = threadIdx.x;
    const int lane = tid & 31;
    const int wid = tid >> 5;
    const int wm = wid & 3;          // 4 warps along M (32 rows each)
    const int wn = (wid >> 2) & 3;   // 4 warps along N (64 cols each)

    float* bias_s = (float*)(smem + BIAS_OFF);
    float* w4_s   = (float*)(smem + W4_OFF);
    float* b4_s   = (float*)(smem + B4_OFF);
    float* oacc   = (float*)(smem + OACC_OFF);

    // prefetch first W chunk of layer 0 (lands during gather)
    issue_chunk(sb, tid, g_wblob + c_lbase[0], 96, 0, 0);

    // stage biases + W4
    if (tid < 256) {
        bias_s[tid] = b0[tid]; bias_s[256 + tid] = b1[tid];
        bias_s[512 + tid] = b2[tid]; bias_s[768 + tid] = b3[tid];
    }
    for (int i = tid; i < 768; i += NTH) w4_s[i] = W4[i];
    if (tid < 3) b4_s[tid] = b4[tid];

    // ---- gather -> A0 (bf16 hi/lo, 128 point-rows, stride 528B) ----
    const int p  = tid & 127;
    const int q  = tid >> 7;   // 4 channel groups of 16 per point
    const int gp = blockIdx.x * MT + p;
    const int b  = gp / (HQv * WQv);
    const int rem = gp % (HQv * WQv);
    const int yq = rem / WQv, xq = rem % WQv;
    const float gy = coord[((size_t)(b * HQv + yq) * WQv + xq) * 2 + 0];
    const float gx = coord[((size_t)(b * HQv + yq) * WQv + xq) * 2 + 1];

    float tx = __fmul_rn(__fadd_rn(__fmul_rn(__fadd_rn(gx, 1.0f), (float)WFv), -1.0f), 0.5f);
    float ty = __fmul_rn(__fadd_rn(__fmul_rn(__fadd_rn(gy, 1.0f), (float)HFv), -1.0f), 0.5f);
    const int ixn = (int)rintf(tx);
    const int iyn = (int)rintf(ty);
    const bool valid = (ixn >= 0) && (ixn < WFv) && (iyn >= 0) && (iyn < HFv);
    const int ixc = min(max(ixn, 0), WFv - 1);
    const int iyc = min(max(iyn, 0), HFv - 1);

    {   // channels q*16 .. q*16+15 -> u32 slots q*8..q*8+7 of row p
        const float* xb = x + (size_t)b * 64 * (HFv * WFv) + (size_t)iyc * WFv + ixc;
        char* rh = smem + A_HI_OFF + (size_t)p * 528 + q * 32;
        char* rl = smem + A_LO_OFF + (size_t)p * 528 + q * 32;
#pragma unroll
        for (int j = 0; j < 8; j++) {
            const int c0 = q * 16 + 2 * j;
            const float f0 = valid ? xb[(size_t)c0 * (HFv * WFv)] : 0.0f;
            const float f1 = valid ? xb[(size_t)(c0 + 1) * (HFv * WFv)] : 0.0f;
            uint32_t hi, lo;
            cvt2(f0, f1, hi, lo);
            *(uint32_t*)(rh + j * 4) = hi;
            *(uint32_t*)(rl + j * 4) = lo;
        }
    }
    if (tid >= 128 && tid < 256) {  // scalar features -> cols 64..95
        float qy = 0.0f, qx = 0.0f;
        if (valid) {
            qy = __fadd_rn(__fdiv_rn(__fadd_rn(__fmul_rn(2.0f, (float)iyc), 1.0f), (float)HFv), -1.0f);
            qx = __fadd_rn(__fdiv_rn(__fadd_rn(__fmul_rn(2.0f, (float)ixc), 1.0f), (float)WFv), -1.0f);
        }
        float vals[32];
#pragma unroll
        for (int i = 0; i < 32; i++) vals[i] = 0.0f;
        vals[0] = __fmul_rn(__fadd_rn(gy, -qy), (float)HFv);
        vals[1] = __fmul_rn(__fadd_rn(gx, -qx), (float)WFv);
        vals[2] = __fmul_rn(cell[b * 2 + 0], (float)HFv);
        vals[3] = __fmul_rn(cell[b * 2 + 1], (float)WFv);
        const float rx = 1.0f / (float)HFv, ry = 1.0f / (float)WFv;
        const float lo_c = -1.0f + 1e-6f, hi_c = 1.0f - 1e-6f;
        float s[3][4];
        int j = 0;
#pragma unroll
        for (int a = 0; a < 2; a++) {
#pragma unroll
            for (int c2 = 0; c2 < 2; c2++) {
                const float vx = a ? 1.0f : -1.0f;
                const float vy = c2 ? 1.0f : -1.0f;
                float cy = __fadd_rn(__fadd_rn(gy, __fmul_rn(vx, rx)), 1e-6f);
                float cx = __fadd_rn(__fadd_rn(gx, __fmul_rn(vy, ry)), 1e-6f);
                cy = fminf(fmaxf(cy, lo_c), hi_c);
                cx = fminf(fmaxf(cx, lo_c), hi_c);
                float fx = __fmul_rn(__fadd_rn(__fmul_rn(__fadd_rn(cx, 1.0f), (float)WFv), -1.0f), 0.5f);
                float fy = __fmul_rn(__fadd_rn(__fmul_rn(__fadd_rn(cy, 1.0f), (float)HFv), -1.0f), 0.5f);
                int jx = min(max((int)rintf(fx), 0), WFv - 1);
                int jy = min(max((int)rintf(fy), 0), HFv - 1);
#pragma unroll
                for (int ch = 0; ch < 3; ch++)
                    s[ch][j] = lr[((size_t)(b * 3 + ch) * HFv + jy) * WFv + jx];
                j++;
            }
        }
#pragma unroll
        for (int ch = 0; ch < 3; ch++) {
            const float m = 0.25f * (s[ch][0] + s[ch][1] + s[ch][2] + s[ch][3]);
            float v = 0.0f;
#pragma unroll
            for (int qq = 0; qq < 4; qq++) { const float d = s[ch][qq] - m; v += d * d; }
            vals[4 + ch] = sqrtf(v * (1.0f / 3.0f));
        }
        char* rh = smem + A_HI_OFF + (size_t)p * 528 + 128;
        char* rl = smem + A_LO_OFF + (size_t)p * 528 + 128;
#pragma unroll
        for (int k = 0; k < 16; k++) {
            uint32_t hi, lo;
            cvt2(vals[2 * k], vals[2 * k + 1], hi, lo);
            *(uint32_t*)(rh + k * 4) = hi;
            *(uint32_t*)(rl + k * 4) = lo;
        }
    }
    __syncthreads();

    // ---- 4 MMA layers, K=32 chunks (hi+lo), 3-pass split ----
    float acc[2][8][4];
    const uint32_t aRowByte = (uint32_t)(wm * 32 + (lane & 15)) * 528 + (lane >> 4) * 16;
    const uint32_t bColByte = (uint32_t)(wn * 64 + (lane >> 4) * 8) * 2;
    const uint32_t bRowByte = (uint32_t)(lane & 15) * 528;

    int g = 0;  // global chunk index (0..26)
#pragma unroll 1
    for (int layer = 0; layer < 4; layer++) {
        const int nch = (layer == 0) ? 3 : 8;
#pragma unroll
        for (int mt = 0; mt < 2; mt++)
#pragma unroll
            for (int nt = 0; nt < 8; nt++)
#pragma unroll
                for (int e = 0; e < 4; e++) acc[mt][nt][e] = 0.0f;

#pragma unroll 1
        for (int c = 0; c < nch; c++, g++) {
            if (g + 1 < 27) {
                // next chunk (possibly next layer's chunk 0)
                const int gn = g + 1;
                const int nl = (gn < 3) ? 0 : 1 + (gn - 3) / 8;
                const int ncc = (gn < 3) ? gn : (gn - 3) & 7;
                issue_chunk(sb, tid, g_wblob + c_lbase[nl], nl ? 256 : 96, ncc, gn & 1);
                asm volatile("cp.async.wait_group 1;" ::: "memory");
            } else {
                asm volatile("cp.async.wait_group 0;" ::: "memory");
            }
            __syncthreads();

            const uint32_t wb = sb + WBUF_OFF + (g & 1) * WBUF_SZ;
#pragma unroll
            for (int kk = 0; kk < 2; kk++) {
                const uint32_t kByte = (uint32_t)(c * 32 + kk * 16) * 2;
                uint32_t ah[2][4], al[2][4];
#pragma unroll
                for (int mt = 0; mt < 2; mt++) {
                    const uint32_t aoff = aRowByte + (uint32_t)(mt * 16) * 528 + kByte;
                    ldsm4(ah[mt], sb + A_HI_OFF + aoff);
                    ldsm4(al[mt], sb + A_LO_OFF + aoff);
                }
#pragma unroll
                for (int ng = 0; ng < 4; ng++) {
                    const uint32_t bo = bRowByte + (uint32_t)(kk * 16) * 528
                                      + bColByte + (uint32_t)(ng * 16) * 2;
                    uint32_t w0, w1, w2, w3;
                    ldsm4t(w0, w1, w2, w3, wb + bo);          // hi W
#pragma unroll
                    for (int mt = 0; mt < 2; mt++) {
                        mma16816(acc[mt][2 * ng],     ah[mt], w0, w1);
                        mma16816(acc[mt][2 * ng + 1], ah[mt], w2, w3);
                        mma16816(acc[mt][2 * ng],     al[mt], w0, w1);
                        mma16816(acc[mt][2 * ng + 1], al[mt], w2, w3);
                    }
                    uint32_t l0, l1, l2, l3;
                    ldsm4t(l0, l1, l2, l3, wb + WPLANE + bo); // lo W
#pragma unroll
                    for (int mt = 0; mt < 2; mt++) {
                        mma16816(acc[mt][2 * ng],     ah[mt], l0, l1);
                        mma16816(acc[mt][2 * ng + 1], ah[mt], l2, l3);
                    }
                }
            }
            __syncthreads();
        }

        const float* bl_bias = bias_s + layer * 256;
        if (layer < 3) {
            // epilogue: relu(D+b) -> bf16 hi/lo back into A (in place)
#pragma unroll
            for (int mt = 0; mt < 2; mt++) {
#pragma unroll
                for (int nt = 0; nt < 8; nt++) {
                    const int r0 = wm * 32 + mt * 16 + (lane >> 2);
                    const int c0 = wn * 64 + nt * 8 + (lane & 3) * 2;
                    const float bb0 = bl_bias[c0], bb1 = bl_bias[c0 + 1];
                    const float h00 = fmaxf(acc[mt][nt][0] + bb0, 0.0f);
                    const float h01 = fmaxf(acc[mt][nt][1] + bb1, 0.0f);
                    const float h10 = fmaxf(acc[mt][nt][2] + bb0, 0.0f);
                    const float h11 = fmaxf(acc[mt][nt][3] + bb1, 0.0f);
                    uint32_t hi, lo;
                    cvt2(h00, h01, hi, lo);
                    *(uint32_t*)(smem + A_HI_OFF + (size_t)r0 * 528 + c0 * 2) = hi;
                    *(uint32_t*)(smem + A_LO_OFF + (size_t)r0 * 528 + c0 * 2) = lo;
                    cvt2(h10, h11, hi, lo);
                    *(uint32_t*)(smem + A_HI_OFF + (size_t)(r0 + 8) * 528 + c0 * 2) = hi;
                    *(uint32_t*)(smem + A_LO_OFF + (size_t)(r0 + 8) * 528 + c0 * 2) = lo;
                }
            }
            // visibility: next layer's first-chunk __syncthreads orders these stores
        } else {
            // final: out = relu(D + b3) @ W4 + b4 (exact fp32)
            if (tid < 384) oacc[tid] = 0.0f;
            __syncthreads();
            float sres[4][3];
#pragma unroll
            for (int ii = 0; ii < 4; ii++)
#pragma unroll
                for (int o = 0; o < 3; o++) sres[ii][o] = 0.0f;
#pragma unroll
            for (int nt = 0; nt < 8; nt++) {
#pragma unroll
                for (int e = 0; e < 2; e++) {
                    const int col = wn * 64 + nt * 8 + (lane & 3) * 2 + e;
                    const float bb = bl_bias[col];
                    const float w40 = w4_s[col * 3 + 0];
                    const float w41 = w4_s[col * 3 + 1];
                    const float w42 = w4_s[col * 3 + 2];
                    const float h0 = fmaxf(acc[0][nt][e] + bb, 0.0f);      // row r
                    const float h1 = fmaxf(acc[0][nt][2 + e] + bb, 0.0f);  // row r+8
                    const float h2 = fmaxf(acc[1][nt][e] + bb, 0.0f);      // row r+16
                    const float h3 = fmaxf(acc[1][nt][2 + e] + bb, 0.0f);  // row r+24
                    sres[0][0] = fmaf(h0, w40, sres[0][0]); sres[0][1] = fmaf(h0, w41, sres[0][1]); sres[0][2] = fmaf(h0, w42, sres[0][2]);
                    sres[1][0] = fmaf(h1, w40, sres[1][0]); sres[1][1] = fmaf(h1, w41, sres[1][1]); sres[1][2] = fmaf(h1, w42, sres[1][2]);
                    sres[2][0] = fmaf(h2, w40, sres[2][0]); sres[2][1] = fmaf(h2, w41, sres[2][1]); sres[2][2] = fmaf(h2, w42, sres[2][2]);
                    sres[3][0] = fmaf(h3, w40, sres[3][0]); sres[3][1] = fmaf(h3, w41, sres[3][1]); sres[3][2] = fmaf(h3, w42, sres[3][2]);
                }
            }
            const int rbase = wm * 32 + (lane >> 2);
#pragma unroll
            for (int ii = 0; ii < 4; ii++) {
                const int row = rbase + ii * 8;
#pragma unroll
                for (int o = 0; o < 3; o++)
                    atomicAdd(&oacc[row * 3 + o], sres[ii][o]);
            }
            __syncthreads();
            if (tid < 128) {
                const size_t base = (size_t)(b * 3) * (HQv * WQv) + (size_t)yq * WQv + xq;
                out[base]                           = oacc[tid * 3 + 0] + b4_s[0];
                out[base + (size_t)(HQv * WQv)]     = oacc[tid * 3 + 1] + b4_s[1];
                out[base + (size_t)(2 * HQv * WQv)] = oacc[tid * 3 + 2] + b4_s[2];
            }
        }
    }
}

// ---------------------------------------------------------------------------
extern "C" void kernel_launch(void* const* d_in, const int* in_sizes, int n_in,
                              void* d_out, int out_size)
{
    const float* x     = (const float*)d_in[0];
    const float* coord = (const float*)d_in[1];
    const float* cell  = (const float*)d_in[2];
    const float* lr    = (const float*)d_in[3];
    const float* W0    = (const float*)d_in[4];
    const float* b0    = (const float*)d_in[5];
    const float* W1    = (const float*)d_in[6];
    const float* b1    = (const float*)d_in[7];
    const float* W2    = (const float*)d_in[8];
    const float* b2    = (const float*)d_in[9];
    const float* W3    = (const float*)d_in[10];
    const float* b3    = (const float*)d_in[11];
    const float* W4    = (const float*)d_in[12];
    const float* b4    = (const float*)d_in[13];
    float* out = (float*)d_out;

    liif_prep_kernel<<<864, 256>>>(W0, W1, W2, W3);

    const int P = out_size / 3;      // 589824
    const int nblk = P / MT;         // 4608

    cudaFuncSetAttribute(liif_hmma_kernel,
                         cudaFuncAttributeMaxDynamicSharedMemorySize, SMEM_TOTAL);
    liif_hmma_kernel<<<nblk, NTH, SMEM_TOTAL>>>(
        x, coord, cell, lr, b0, b1, b2, b3, W4, b4, out);
}

// round 6
// speedup vs baseline: 1.0731x; 1.0007x over previous
#include <cuda_runtime.h>
#include <cuda_bf16.h>
#include <cstdint>

// ============================================================================
// LIIF sampler via mma.sync bf16 3-pass split. Round 6: R5 structure with
// pass-major MMA ordering inside each ng tile (same-acc RAW gap 1 -> 4 instrs)
// to break HMMA accumulator dependency chains. Register-neutral change.
// ============================================================================

#define HQv 384
#define WQv 384
#define HFv 48
#define WFv 48

#define MT  128
#define NTH 512

// smem layout (bytes)
#define A_HI_OFF 0
#define A_LO_OFF (128 * 528)                 // 67584
#define WBUF_OFF (2 * 128 * 528)             // 135168
#define WPLANE   (32 * 528)                  // 16896
#define WBUF_SZ  (2 * WPLANE)                // 33792 (hi+lo)
#define BIAS_OFF (WBUF_OFF + 2 * WBUF_SZ)    // 202752
#define W4_OFF   (BIAS_OFF + 4096)           // 206848
#define B4_OFF   (W4_OFF + 3072)             // 209920
#define OACC_OFF (B4_OFF + 16)               // 209936
#define SMEM_TOTAL (OACC_OFF + 1536)         // 211472

// weight blob: per layer, hi plane [kpad][256] bf16 then lo plane.
__device__ __align__(128) unsigned char g_wblob[884736];
__constant__ int c_lbase[4] = {0, 98304, 360448, 622592};

// ---------------------------------------------------------------------------
__device__ __forceinline__ uint32_t smem_u32(const void* p) {
    uint32_t a;
    asm("{ .reg .u64 t; cvta.to.shared.u64 t, %1; cvt.u32.u64 %0, t; }"
        : "=r"(a) : "l"(p));
    return a;
}
__device__ __forceinline__ void ldsm4(uint32_t* r, uint32_t a) {
    asm volatile("ldmatrix.sync.aligned.m8n8.x4.shared.b16 {%0,%1,%2,%3}, [%4];"
                 : "=r"(r[0]), "=r"(r[1]), "=r"(r[2]), "=r"(r[3]) : "r"(a));
}
__device__ __forceinline__ void ldsm4t(uint32_t& r0, uint32_t& r1, uint32_t& r2,
                                       uint32_t& r3, uint32_t a) {
    asm volatile("ldmatrix.sync.aligned.m8n8.x4.trans.shared.b16 {%0,%1,%2,%3}, [%4];"
                 : "=r"(r0), "=r"(r1), "=r"(r2), "=r"(r3) : "r"(a));
}
__device__ __forceinline__ void mma16816(float* d, const uint32_t* a,
                                         uint32_t b0, uint32_t b1) {
    asm volatile(
        "mma.sync.aligned.m16n8k16.row.col.f32.bf16.bf16.f32 "
        "{%0,%1,%2,%3}, {%4,%5,%6,%7}, {%8,%9}, {%0,%1,%2,%3};"
        : "+f"(d[0]), "+f"(d[1]), "+f"(d[2]), "+f"(d[3])
        : "r"(a[0]), "r"(a[1]), "r"(a[2]), "r"(a[3]), "r"(b0), "r"(b1));
}
__device__ __forceinline__ void cpasync16(uint32_t dst, const void* src) {
    asm volatile("cp.async.cg.shared.global [%0], [%1], 16;"
                 :: "r"(dst), "l"(src) : "memory");
}
__device__ __forceinline__ void cp_commit() {
    asm volatile("cp.async.commit_group;" ::: "memory");
}
__device__ __forceinline__ void cvt2(float a, float b, uint32_t& hi, uint32_t& lo) {
    __nv_bfloat16 ah = __float2bfloat16(a), bh = __float2bfloat16(b);
    __nv_bfloat16 al = __float2bfloat16(a - __bfloat162float(ah));
    __nv_bfloat16 bl = __float2bfloat16(b - __bfloat162float(bh));
    hi = (uint32_t)__bfloat16_as_ushort(ah) | ((uint32_t)__bfloat16_as_ushort(bh) << 16);
    lo = (uint32_t)__bfloat16_as_ushort(al) | ((uint32_t)__bfloat16_as_ushort(bl) << 16);
}

// stage one K=32 chunk (hi plane + lo plane) into wbuf[bsel]
__device__ __forceinline__ void issue_chunk(uint32_t sb, int tid,
                                            const unsigned char* lbase, int kpad,
                                            int c, int bsel)
{
#pragma unroll
    for (int it = 0; it < 4; it++) {
        const int i = tid + it * NTH;
        const int pl = i >> 10;
        const int r = (i >> 5) & 31;
        const int s = i & 31;
        const unsigned char* src = lbase + (size_t)pl * ((size_t)kpad * 512)
                                 + (size_t)(c * 32 + r) * 512 + s * 16;
        const uint32_t dst = sb + WBUF_OFF + bsel * WBUF_SZ + pl * WPLANE + r * 528 + s * 16;
        cpasync16(dst, src);
    }
    cp_commit();
}

// ---------------------------------------------------------------------------
// Prep: split W0..W3 fp32 -> bf16 hi/lo planes in g_wblob.
// ---------------------------------------------------------------------------
__global__ void liif_prep_kernel(const float* __restrict__ W0, const float* __restrict__ W1,
                                 const float* __restrict__ W2, const float* __restrict__ W3)
{
    const int row = blockIdx.x;       // 0..863
    const int n = threadIdx.x;
    int layer, k;
    if (row < 96) { layer = 0; k = row; }
    else { layer = 1 + (row - 96) / 256; k = (row - 96) & 255; }
    const float* W = (layer == 0) ? W0 : (layer == 1) ? W1 : (layer == 2) ? W2 : W3;
    const int Kl = (layer == 0) ? 71 : 256;
    const int kpad = (layer == 0) ? 96 : 256;
    const float val = (k < Kl) ? W[k * 256 + n] : 0.0f;
    __nv_bfloat16 hi = __float2bfloat16(val);
    __nv_bfloat16 lo = __float2bfloat16(val - __bfloat162float(hi));
    unsigned char* base = g_wblob + c_lbase[layer];
    *(unsigned short*)(base + (size_t)k * 512 + n * 2) = __bfloat16_as_ushort(hi);
    *(unsigned short*)(base + (size_t)kpad * 512 + (size_t)k * 512 + n * 2) =
        __bfloat16_as_ushort(lo);
}

// ---------------------------------------------------------------------------
__global__ __launch_bounds__(NTH, 1)
void liif_hmma_kernel(
    const float* __restrict__ x, const float* __restrict__ coord,
    const float* __restrict__ cell, const float* __restrict__ lr,
    const float* __restrict__ b0, const float* __restrict__ b1,
    const float* __restrict__ b2, const float* __restrict__ b3,
    const float* __restrict__ W4, const float* __restrict__ b4,
    float* __restrict__ out)
{
    extern __shared__ __align__(16) char smem[];
    const uint32_t sb = smem_u32(smem);
    const int tid = threadIdx.x;
    const int lane = tid & 31;
    const int wid = tid >> 5;
    const int wm = wid & 3;          // 4 warps along M (32 rows each)
    const int wn = (wid >> 2) & 3;   // 4 warps along N (64 cols each)

    float* bias_s = (float*)(smem + BIAS_OFF);
    float* w4_s   = (float*)(smem + W4_OFF);
    float* b4_s   = (float*)(smem + B4_OFF);
    float* oacc   = (float*)(smem + OACC_OFF);

    // prefetch first W chunk of layer 0 (lands during gather)
    issue_chunk(sb, tid, g_wblob + c_lbase[0], 96, 0, 0);

    // stage biases + W4
    if (tid < 256) {
        bias_s[tid] = b0[tid]; bias_s[256 + tid] = b1[tid];
        bias_s[512 + tid] = b2[tid]; bias_s[768 + tid] = b3[tid];
    }
    for (int i = tid; i < 768; i += NTH) w4_s[i] = W4[i];
    if (tid < 3) b4_s[tid] = b4[tid];

    // ---- gather -> A0 (bf16 hi/lo, 128 point-rows, stride 528B) ----
    const int p  = tid & 127;
    const int q  = tid >> 7;   // 4 channel groups of 16 per point
    const int gp = blockIdx.x * MT + p;
    const int b  = gp / (HQv * WQv);
    const int rem = gp % (HQv * WQv);
    const int yq = rem / WQv, xq = rem % WQv;
    const float gy = coord[((size_t)(b * HQv + yq) * WQv + xq) * 2 + 0];
    const float gx = coord[((size_t)(b * HQv + yq) * WQv + xq) * 2 + 1];

    float tx = __fmul_rn(__fadd_rn(__fmul_rn(__fadd_rn(gx, 1.0f), (float)WFv), -1.0f), 0.5f);
    float ty = __fmul_rn(__fadd_rn(__fmul_rn(__fadd_rn(gy, 1.0f), (float)HFv), -1.0f), 0.5f);
    const int ixn = (int)rintf(tx);
    const int iyn = (int)rintf(ty);
    const bool valid = (ixn >= 0) && (ixn < WFv) && (iyn >= 0) && (iyn < HFv);
    const int ixc = min(max(ixn, 0), WFv - 1);
    const int iyc = min(max(iyn, 0), HFv - 1);

    {   // channels q*16 .. q*16+15 -> u32 slots q*8..q*8+7 of row p
        const float* xb = x + (size_t)b * 64 * (HFv * WFv) + (size_t)iyc * WFv + ixc;
        char* rh = smem + A_HI_OFF + (size_t)p * 528 + q * 32;
        char* rl = smem + A_LO_OFF + (size_t)p * 528 + q * 32;
#pragma unroll
        for (int j = 0; j < 8; j++) {
            const int c0 = q * 16 + 2 * j;
            const float f0 = valid ? xb[(size_t)c0 * (HFv * WFv)] : 0.0f;
            const float f1 = valid ? xb[(size_t)(c0 + 1) * (HFv * WFv)] : 0.0f;
            uint32_t hi, lo;
            cvt2(f0, f1, hi, lo);
            *(uint32_t*)(rh + j * 4) = hi;
            *(uint32_t*)(rl + j * 4) = lo;
        }
    }
    if (tid >= 128 && tid < 256) {  // scalar features -> cols 64..95
        float qy = 0.0f, qx = 0.0f;
        if (valid) {
            qy = __fadd_rn(__fdiv_rn(__fadd_rn(__fmul_rn(2.0f, (float)iyc), 1.0f), (float)HFv), -1.0f);
            qx = __fadd_rn(__fdiv_rn(__fadd_rn(__fmul_rn(2.0f, (float)ixc), 1.0f), (float)WFv), -1.0f);
        }
        float vals[32];
#pragma unroll
        for (int i = 0; i < 32; i++) vals[i] = 0.0f;
        vals[0] = __fmul_rn(__fadd_rn(gy, -qy), (float)HFv);
        vals[1] = __fmul_rn(__fadd_rn(gx, -qx), (float)WFv);
        vals[2] = __fmul_rn(cell[b * 2 + 0], (float)HFv);
        vals[3] = __fmul_rn(cell[b * 2 + 1], (float)WFv);
        const float rx = 1.0f / (float)HFv, ry = 1.0f / (float)WFv;
        const float lo_c = -1.0f + 1e-6f, hi_c = 1.0f - 1e-6f;
        float s[3][4];
        int j = 0;
#pragma unroll
        for (int a = 0; a < 2; a++) {
#pragma unroll
            for (int c2 = 0; c2 < 2; c2++) {
                const float vx = a ? 1.0f : -1.0f;
                const float vy = c2 ? 1.0f : -1.0f;
                float cy = __fadd_rn(__fadd_rn(gy, __fmul_rn(vx, rx)), 1e-6f);
                float cx = __fadd_rn(__fadd_rn(gx, __fmul_rn(vy, ry)), 1e-6f);
                cy = fminf(fmaxf(cy, lo_c), hi_c);
                cx = fminf(fmaxf(cx, lo_c), hi_c);
                float fx = __fmul_rn(__fadd_rn(__fmul_rn(__fadd_rn(cx, 1.0f), (float)WFv), -1.0f), 0.5f);
                float fy = __fmul_rn(__fadd_rn(__fmul_rn(__fadd_rn(cy, 1.0f), (float)HFv), -1.0f), 0.5f);
                int jx = min(max((int)rintf(fx), 0), WFv - 1);
                int jy = min(max((int)rintf(fy), 0), HFv - 1);
#pragma unroll
                for (int ch = 0; ch < 3; ch++)
                    s[ch][j] = lr[((size_t)(b * 3 + ch) * HFv + jy) * WFv + jx];
                j++;
            }
        }
#pragma unroll
        for (int ch = 0; ch < 3; ch++) {
            const float m = 0.25f * (s[ch][0] + s[ch][1] + s[ch][2] + s[ch][3]);
            float v = 0.0f;
#pragma unroll
            for (int qq = 0; qq < 4; qq++) { const float d = s[ch][qq] - m; v += d * d; }
            vals[4 + ch] = sqrtf(v * (1.0f / 3.0f));
        }
        char* rh = smem + A_HI_OFF + (size_t)p * 528 + 128;
        char* rl = smem + A_LO_OFF + (size_t)p * 528 + 128;
#pragma unroll
        for (int k = 0; k < 16; k++) {
            uint32_t hi, lo;
            cvt2(vals[2 * k], vals[2 * k + 1], hi, lo);
            *(uint32_t*)(rh + k * 4) = hi;
            *(uint32_t*)(rl + k * 4) = lo;
        }
    }
    __syncthreads();

    // ---- 4 MMA layers, K=32 chunks (hi+lo), 3-pass split, pass-major order ----
    float acc[2][8][4];
    const uint32_t aRowByte = (uint32_t)(wm * 32 + (lane & 15)) * 528 + (lane >> 4) * 16;
    const uint32_t bColByte = (uint32_t)(wn * 64 + (lane >> 4) * 8) * 2;
    const uint32_t bRowByte = (uint32_t)(lane & 15) * 528;

    int g = 0;  // global chunk index (0..26)
#pragma unroll 1
    for (int layer = 0; layer < 4; layer++) {
        const int nch = (layer == 0) ? 3 : 8;
#pragma unroll
        for (int mt = 0; mt < 2; mt++)
#pragma unroll
            for (int nt = 0; nt < 8; nt++)
#pragma unroll
                for (int e = 0; e < 4; e++) acc[mt][nt][e] = 0.0f;

#pragma unroll 1
        for (int c = 0; c < nch; c++, g++) {
            if (g + 1 < 27) {
                const int gn = g + 1;
                const int nl = (gn < 3) ? 0 : 1 + (gn - 3) / 8;
                const int ncc = (gn < 3) ? gn : (gn - 3) & 7;
                issue_chunk(sb, tid, g_wblob + c_lbase[nl], nl ? 256 : 96, ncc, gn & 1);
                asm volatile("cp.async.wait_group 1;" ::: "memory");
            } else {
                asm volatile("cp.async.wait_group 0;" ::: "memory");
            }
            __syncthreads();

            const uint32_t wb = sb + WBUF_OFF + (g & 1) * WBUF_SZ;
#pragma unroll
            for (int kk = 0; kk < 2; kk++) {
                const uint32_t kByte = (uint32_t)(c * 32 + kk * 16) * 2;
                uint32_t ah[2][4], al[2][4];
#pragma unroll
                for (int mt = 0; mt < 2; mt++) {
                    const uint32_t aoff = aRowByte + (uint32_t)(mt * 16) * 528 + kByte;
                    ldsm4(ah[mt], sb + A_HI_OFF + aoff);
                    ldsm4(al[mt], sb + A_LO_OFF + aoff);
                }
#pragma unroll
                for (int ng = 0; ng < 4; ng++) {
                    const uint32_t bo = bRowByte + (uint32_t)(kk * 16) * 528
                                      + bColByte + (uint32_t)(ng * 16) * 2;
                    uint32_t w0, w1, w2, w3;
                    ldsm4t(w0, w1, w2, w3, wb + bo);          // hi W
                    // pass 1: ah * w_hi  (4 distinct accs)
                    mma16816(acc[0][2 * ng],     ah[0], w0, w1);
                    mma16816(acc[0][2 * ng + 1], ah[0], w2, w3);
                    mma16816(acc[1][2 * ng],     ah[1], w0, w1);
                    mma16816(acc[1][2 * ng + 1], ah[1], w2, w3);
                    // pass 2: al * w_hi  (same accs, gap 4)
                    mma16816(acc[0][2 * ng],     al[0], w0, w1);
                    mma16816(acc[0][2 * ng + 1], al[0], w2, w3);
                    mma16816(acc[1][2 * ng],     al[1], w0, w1);
                    mma16816(acc[1][2 * ng + 1], al[1], w2, w3);
                    // pass 3: ah * w_lo  (ldsm interposed, gap 4)
                    uint32_t l0, l1, l2, l3;
                    ldsm4t(l0, l1, l2, l3, wb + WPLANE + bo); // lo W
                    mma16816(acc[0][2 * ng],     ah[0], l0, l1);
                    mma16816(acc[0][2 * ng + 1], ah[0], l2, l3);
                    mma16816(acc[1][2 * ng],     ah[1], l0, l1);
                    mma16816(acc[1][2 * ng + 1], ah[1], l2, l3);
                }
            }
            __syncthreads();
        }

        const float* bl_bias = bias_s + layer * 256;
        if (layer < 3) {
            // epilogue: relu(D+b) -> bf16 hi/lo back into A (in place)
#pragma unroll
            for (int mt = 0; mt < 2; mt++) {
#pragma unroll
                for (int nt = 0; nt < 8; nt++) {
                    const int r0 = wm * 32 + mt * 16 + (lane >> 2);
                    const int c0 = wn * 64 + nt * 8 + (lane & 3) * 2;
                    const float bb0 = bl_bias[c0], bb1 = bl_bias[c0 + 1];
                    const float h00 = fmaxf(acc[mt][nt][0] + bb0, 0.0f);
                    const float h01 = fmaxf(acc[mt][nt][1] + bb1, 0.0f);
                    const float h10 = fmaxf(acc[mt][nt][2] + bb0, 0.0f);
                    const float h11 = fmaxf(acc[mt][nt][3] + bb1, 0.0f);
                    uint32_t hi, lo;
                    cvt2(h00, h01, hi, lo);
                    *(uint32_t*)(smem + A_HI_OFF + (size_t)r0 * 528 + c0 * 2) = hi;
                    *(uint32_t*)(smem + A_LO_OFF + (size_t)r0 * 528 + c0 * 2) = lo;
                    cvt2(h10, h11, hi, lo);
                    *(uint32_t*)(smem + A_HI_OFF + (size_t)(r0 + 8) * 528 + c0 * 2) = hi;
                    *(uint32_t*)(smem + A_LO_OFF + (size_t)(r0 + 8) * 528 + c0 * 2) = lo;
                }
            }
            // visibility: next layer's first-chunk __syncthreads orders these stores
        } else {
            // final: out = relu(D + b3) @ W4 + b4 (exact fp32)
            if (tid < 384) oacc[tid] = 0.0f;
            __syncthreads();
            float sres[4][3];
#pragma unroll
            for (int ii = 0; ii < 4; ii++)
#pragma unroll
                for (int o = 0; o < 3; o++) sres[ii][o] = 0.0f;
#pragma unroll
            for (int nt = 0; nt < 8; nt++) {
#pragma unroll
                for (int e = 0; e < 2; e++) {
                    const int col = wn * 64 + nt * 8 + (lane & 3) * 2 + e;
                    const float bb = bl_bias[col];
                    const float w40 = w4_s[col * 3 + 0];
                    const float w41 = w4_s[col * 3 + 1];
                    const float w42 = w4_s[col * 3 + 2];
                    const float h0 = fmaxf(acc[0][nt][e] + bb, 0.0f);
                    const float h1 = fmaxf(acc[0][nt][2 + e] + bb, 0.0f);
                    const float h2 = fmaxf(acc[1][nt][e] + bb, 0.0f);
                    const float h3 = fmaxf(acc[1][nt][2 + e] + bb, 0.0f);
                    sres[0][0] = fmaf(h0, w40, sres[0][0]); sres[0][1] = fmaf(h0, w41, sres[0][1]); sres[0][2] = fmaf(h0, w42, sres[0][2]);
                    sres[1][0] = fmaf(h1, w40, sres[1][0]); sres[1][1] = fmaf(h1, w41, sres[1][1]); sres[1][2] = fmaf(h1, w42, sres[1][2]);
                    sres[2][0] = fmaf(h2, w40, sres[2][0]); sres[2][1] = fmaf(h2, w41, sres[2][1]); sres[2][2] = fmaf(h2, w42, sres[2][2]);
                    sres[3][0] = fmaf(h3, w40, sres[3][0]); sres[3][1] = fmaf(h3, w41, sres[3][1]); sres[3][2] = fmaf(h3, w42, sres[3][2]);
                }
            }
            const int rbase = wm * 32 + (lane >> 2);
#pragma unroll
            for (int ii = 0; ii < 4; ii++) {
                const int row = rbase + ii * 8;
#pragma unroll
                for (int o = 0; o < 3; o++)
                    atomicAdd(&oacc[row * 3 + o], sres[ii][o]);
            }
            __syncthreads();
            if (tid < 128) {
                const size_t base = (size_t)(b * 3) * (HQv * WQv) + (size_t)yq * WQv + xq;
                out[base]                           = oacc[tid * 3 + 0] + b4_s[0];
                out[base + (size_t)(HQv * WQv)]     = oacc[tid * 3 + 1] + b4_s[1];
                out[base + (size_t)(2 * HQv * WQv)] = oacc[tid * 3 + 2] + b4_s[2];
            }
        }
    }
}

// ---------------------------------------------------------------------------
extern "C" void kernel_launch(void* const* d_in, const int* in_sizes, int n_in,
                              void* d_out, int out_size)
{
    const float* x     = (const float*)d_in[0];
    const float* coord = (const float*)d_in[1];
    const float* cell  = (const float*)d_in[2];
    const float* lr    = (const float*)d_in[3];
    const float* W0    = (const float*)d_in[4];
    const float* b0    = (const float*)d_in[5];
    const float* W1    = (const float*)d_in[6];
    const float* b1    = (const float*)d_in[7];
    const float* W2    = (const float*)d_in[8];
    const float* b2    = (const float*)d_in[9];
    const float* W3    = (const float*)d_in[10];
    const float* b3    = (const float*)d_in[11];
    const float* W4    = (const float*)d_in[12];
    const float* b4    = (const float*)d_in[13];
    float* out = (float*)d_out;

    liif_prep_kernel<<<864, 256>>>(W0, W1, W2, W3);

    const int P = out_size / 3;      // 589824
    const int nblk = P / MT;         // 4608

    cudaFuncSetAttribute(liif_hmma_kernel,
                         cudaFuncAttributeMaxDynamicSharedMemorySize, SMEM_TOTAL);
    liif_hmma_kernel<<<nblk, NTH, SMEM_TOTAL>>>(
        x, coord, cell, lr, b0, b1, b2, b3, W4, b4, out);
}

// round 7
// speedup vs baseline: 1.4719x; 1.3717x over previous
#include <cuda_runtime.h>
#include <cuda_fp16.h>
#include <cstdint>

// ============================================================================
// LIIF sampler via mma.sync fp16 2-pass (activations split hi/lo, W single
// fp16 plane). 128-pt CTAs, 512 threads, K=64 double-buffered W chunks,
// ONE barrier per phase. Final 256->3 layer exact fp32.
// ============================================================================

#define HQv 384
#define WQv 384
#define HFv 48
#define WFv 48

#define MT  128
#define NTH 512

// smem layout (bytes)
#define A_HI_OFF 0
#define A_LO_OFF (128 * 528)                 // 67584
#define WBUF_OFF (2 * 128 * 528)             // 135168
#define WCHUNK   (64 * 528)                  // 33792 (K=64 rows, single plane)
#define BIAS_OFF (WBUF_OFF + 2 * WCHUNK)     // 202752
#define W4_OFF   (BIAS_OFF + 4096)           // 206848
#define B4_OFF   (W4_OFF + 3072)             // 209920
#define OACC_OFF (B4_OFF + 16)               // 209936
#define SMEM_TOTAL (OACC_OFF + 1536)         // 211472

// weight blob: per layer one fp16 plane [kpad][256]. kpad: L0=128, L1..3=256.
__device__ __align__(128) unsigned char g_wblob[458752];
__constant__ int c_lbase[4] = {0, 65536, 196608, 327680};

// ---------------------------------------------------------------------------
__device__ __forceinline__ uint32_t smem_u32(const void* p) {
    uint32_t a;
    asm("{ .reg .u64 t; cvta.to.shared.u64 t, %1; cvt.u32.u64 %0, t; }"
        : "=r"(a) : "l"(p));
    return a;
}
__device__ __forceinline__ void ldsm4(uint32_t* r, uint32_t a) {
    asm volatile("ldmatrix.sync.aligned.m8n8.x4.shared.b16 {%0,%1,%2,%3}, [%4];"
                 : "=r"(r[0]), "=r"(r[1]), "=r"(r[2]), "=r"(r[3]) : "r"(a));
}
__device__ __forceinline__ void ldsm4t(uint32_t& r0, uint32_t& r1, uint32_t& r2,
                                       uint32_t& r3, uint32_t a) {
    asm volatile("ldmatrix.sync.aligned.m8n8.x4.trans.shared.b16 {%0,%1,%2,%3}, [%4];"
                 : "=r"(r0), "=r"(r1), "=r"(r2), "=r"(r3) : "r"(a));
}
__device__ __forceinline__ void mma16816h(float* d, const uint32_t* a,
                                          uint32_t b0, uint32_t b1) {
    asm volatile(
        "mma.sync.aligned.m16n8k16.row.col.f32.f16.f16.f32 "
        "{%0,%1,%2,%3}, {%4,%5,%6,%7}, {%8,%9}, {%0,%1,%2,%3};"
        : "+f"(d[0]), "+f"(d[1]), "+f"(d[2]), "+f"(d[3])
        : "r"(a[0]), "r"(a[1]), "r"(a[2]), "r"(a[3]), "r"(b0), "r"(b1));
}
__device__ __forceinline__ void cpasync16(uint32_t dst, const void* src) {
    asm volatile("cp.async.cg.shared.global [%0], [%1], 16;"
                 :: "r"(dst), "l"(src) : "memory");
}
__device__ __forceinline__ void cp_commit() {
    asm volatile("cp.async.commit_group;" ::: "memory");
}
// float pair -> fp16 hi/lo packed pairs
__device__ __forceinline__ void cvt2h(float a, float b, uint32_t& hi, uint32_t& lo) {
    __half ah = __float2half_rn(a), bh = __float2half_rn(b);
    __half al = __float2half_rn(a - __half2float(ah));
    __half bl = __float2half_rn(b - __half2float(bh));
    hi = (uint32_t)__half_as_ushort(ah) | ((uint32_t)__half_as_ushort(bh) << 16);
    lo = (uint32_t)__half_as_ushort(al) | ((uint32_t)__half_as_ushort(bl) << 16);
}

// global chunk index g (0..13) -> layer / local chunk
__device__ __forceinline__ void chunk_of(int g, int& layer, int& c) {
    if (g < 2) { layer = 0; c = g; }
    else { layer = 1 + (g - 2) / 4; c = (g - 2) & 3; }
}
// stage one K=64 W chunk into wbuf[bsel]
__device__ __forceinline__ void issue_chunk(uint32_t sb, int tid, int g, int bsel) {
    int layer, c;
    chunk_of(g, layer, c);
    const unsigned char* src0 = g_wblob + c_lbase[layer] + (size_t)c * 32768;
#pragma unroll
    for (int it = 0; it < 4; it++) {
        const int i = tid + it * NTH;     // 0..2047
        const int r = i >> 5, s = i & 31;
        cpasync16(sb + WBUF_OFF + bsel * WCHUNK + r * 528 + s * 16,
                  src0 + (size_t)r * 512 + s * 16);
    }
    cp_commit();
}

// ---------------------------------------------------------------------------
// Prep: W0..W3 fp32 -> single fp16 plane each in g_wblob.
// grid 896 x 256: row 0..127 = L0 (k<71 real), then 3x256 rows.
// ---------------------------------------------------------------------------
__global__ void liif_prep_kernel(const float* __restrict__ W0, const float* __restrict__ W1,
                                 const float* __restrict__ W2, const float* __restrict__ W3)
{
    const int row = blockIdx.x;
    const int n = threadIdx.x;
    int layer, k;
    if (row < 128) { layer = 0; k = row; }
    else { layer = 1 + (row - 128) / 256; k = (row - 128) & 255; }
    const float* W = (layer == 0) ? W0 : (layer == 1) ? W1 : (layer == 2) ? W2 : W3;
    const int Kl = (layer == 0) ? 71 : 256;
    const float val = (k < Kl) ? W[k * 256 + n] : 0.0f;
    *(unsigned short*)(g_wblob + c_lbase[layer] + (size_t)k * 512 + n * 2) =
        __half_as_ushort(__float2half_rn(val));
}

// ---------------------------------------------------------------------------
__global__ __launch_bounds__(NTH, 1)
void liif_hmma_kernel(
    const float* __restrict__ x, const float* __restrict__ coord,
    const float* __restrict__ cell, const float* __restrict__ lr,
    const float* __restrict__ b0, const float* __restrict__ b1,
    const float* __restrict__ b2, const float* __restrict__ b3,
    const float* __restrict__ W4, const float* __restrict__ b4,
    float* __restrict__ out)
{
    extern __shared__ __align__(16) char smem[];
    const uint32_t sb = smem_u32(smem);
    const int tid = threadIdx.x;
    const int lane = tid & 31;
    const int wid = tid >> 5;
    const int wm = wid & 3;          // 4 warps along M (32 rows each)
    const int wn = (wid >> 2) & 3;   // 4 warps along N (64 cols each)

    float* bias_s = (float*)(smem + BIAS_OFF);
    float* w4_s   = (float*)(smem + W4_OFF);
    float* b4_s   = (float*)(smem + B4_OFF);
    float* oacc   = (float*)(smem + OACC_OFF);

    // prefetch W chunk 0 (lands during gather)
    issue_chunk(sb, tid, 0, 0);

    // stage biases + W4
    if (tid < 256) {
        bias_s[tid] = b0[tid]; bias_s[256 + tid] = b1[tid];
        bias_s[512 + tid] = b2[tid]; bias_s[768 + tid] = b3[tid];
    }
    for (int i = tid; i < 768; i += NTH) w4_s[i] = W4[i];
    if (tid < 3) b4_s[tid] = b4[tid];

    // ---- gather -> A0 (fp16 hi/lo, 128 point-rows, stride 528B) ----
    const int p  = tid & 127;
    const int q  = tid >> 7;   // 0..3
    const int gp = blockIdx.x * MT + p;
    const int b  = gp / (HQv * WQv);
    const int rem = gp % (HQv * WQv);
    const int yq = rem / WQv, xq = rem % WQv;
    const float gy = coord[((size_t)(b * HQv + yq) * WQv + xq) * 2 + 0];
    const float gx = coord[((size_t)(b * HQv + yq) * WQv + xq) * 2 + 1];

    float tx = __fmul_rn(__fadd_rn(__fmul_rn(__fadd_rn(gx, 1.0f), (float)WFv), -1.0f), 0.5f);
    float ty = __fmul_rn(__fadd_rn(__fmul_rn(__fadd_rn(gy, 1.0f), (float)HFv), -1.0f), 0.5f);
    const int ixn = (int)rintf(tx);
    const int iyn = (int)rintf(ty);
    const bool valid = (ixn >= 0) && (ixn < WFv) && (iyn >= 0) && (iyn < HFv);
    const int ixc = min(max(ixn, 0), WFv - 1);
    const int iyc = min(max(iyn, 0), HFv - 1);

    if (q < 2) {   // channels q*32 .. q*32+31 -> u32 slots q*16..q*16+15
        const float* xb = x + (size_t)b * 64 * (HFv * WFv) + (size_t)iyc * WFv + ixc;
        char* rh = smem + A_HI_OFF + (size_t)p * 528 + q * 64;
        char* rl = smem + A_LO_OFF + (size_t)p * 528 + q * 64;
#pragma unroll
        for (int j = 0; j < 16; j++) {
            const int c0 = q * 32 + 2 * j;
            const float f0 = valid ? xb[(size_t)c0 * (HFv * WFv)] : 0.0f;
            const float f1 = valid ? xb[(size_t)(c0 + 1) * (HFv * WFv)] : 0.0f;
            uint32_t hi, lo;
            cvt2h(f0, f1, hi, lo);
            *(uint32_t*)(rh + j * 4) = hi;
            *(uint32_t*)(rl + j * 4) = lo;
        }
    } else if (q == 2) {  // scalar features -> cols 64..95
        float qy = 0.0f, qx = 0.0f;
        if (valid) {
            qy = __fadd_rn(__fdiv_rn(__fadd_rn(__fmul_rn(2.0f, (float)iyc), 1.0f), (float)HFv), -1.0f);
            qx = __fadd_rn(__fdiv_rn(__fadd_rn(__fmul_rn(2.0f, (float)ixc), 1.0f), (float)WFv), -1.0f);
        }
        float vals[32];
#pragma unroll
        for (int i = 0; i < 32; i++) vals[i] = 0.0f;
        vals[0] = __fmul_rn(__fadd_rn(gy, -qy), (float)HFv);
        vals[1] = __fmul_rn(__fadd_rn(gx, -qx), (float)WFv);
        vals[2] = __fmul_rn(cell[b * 2 + 0], (float)HFv);
        vals[3] = __fmul_rn(cell[b * 2 + 1], (float)WFv);
        const float rx = 1.0f / (float)HFv, ry = 1.0f / (float)WFv;
        const float lo_c = -1.0f + 1e-6f, hi_c = 1.0f - 1e-6f;
        float s[3][4];
        int j = 0;
#pragma unroll
        for (int a = 0; a < 2; a++) {
#pragma unroll
            for (int c2 = 0; c2 < 2; c2++) {
                const float vx = a ? 1.0f : -1.0f;
                const float vy = c2 ? 1.0f : -1.0f;
                float cy = __fadd_rn(__fadd_rn(gy, __fmul_rn(vx, rx)), 1e-6f);
                float cx = __fadd_rn(__fadd_rn(gx, __fmul_rn(vy, ry)), 1e-6f);
                cy = fminf(fmaxf(cy, lo_c), hi_c);
                cx = fminf(fmaxf(cx, lo_c), hi_c);
                float fx = __fmul_rn(__fadd_rn(__fmul_rn(__fadd_rn(cx, 1.0f), (float)WFv), -1.0f), 0.5f);
                float fy = __fmul_rn(__fadd_rn(__fmul_rn(__fadd_rn(cy, 1.0f), (float)HFv), -1.0f), 0.5f);
                int jx = min(max((int)rintf(fx), 0), WFv - 1);
                int jy = min(max((int)rintf(fy), 0), HFv - 1);
#pragma unroll
                for (int ch = 0; ch < 3; ch++)
                    s[ch][j] = lr[((size_t)(b * 3 + ch) * HFv + jy) * WFv + jx];
                j++;
            }
        }
#pragma unroll
        for (int ch = 0; ch < 3; ch++) {
            const float m = 0.25f * (s[ch][0] + s[ch][1] + s[ch][2] + s[ch][3]);
            float v = 0.0f;
#pragma unroll
            for (int qq = 0; qq < 4; qq++) { const float d = s[ch][qq] - m; v += d * d; }
            vals[4 + ch] = sqrtf(v * (1.0f / 3.0f));
        }
        char* rh = smem + A_HI_OFF + (size_t)p * 528 + 128;
        char* rl = smem + A_LO_OFF + (size_t)p * 528 + 128;
#pragma unroll
        for (int k = 0; k < 16; k++) {
            uint32_t hi, lo;
            cvt2h(vals[2 * k], vals[2 * k + 1], hi, lo);
            *(uint32_t*)(rh + k * 4) = hi;
            *(uint32_t*)(rl + k * 4) = lo;
        }
    } else {  // q == 3: zero-pad A cols 96..127 (both planes) for L0 kpad=128
        uint4 z = {0u, 0u, 0u, 0u};
        uint4* zh = (uint4*)(smem + A_HI_OFF + (size_t)p * 528 + 192);
        uint4* zl = (uint4*)(smem + A_LO_OFF + (size_t)p * 528 + 192);
        zh[0] = z; zh[1] = z; zh[2] = z; zh[3] = z;
        zl[0] = z; zl[1] = z; zl[2] = z; zl[3] = z;
    }

    // ---- 4 MMA layers, K=64 chunks, fp16 2-pass, one barrier per phase ----
    float acc[2][8][4];
    const uint32_t aRowByte = (uint32_t)(wm * 32 + (lane & 15)) * 528 + (lane >> 4) * 16;
    const uint32_t bColByte = (uint32_t)(wn * 64 + (lane >> 4) * 8) * 2;
    const uint32_t bRowByte = (uint32_t)(lane & 15) * 528;

    int g = 0;  // global chunk index (0..13)
#pragma unroll 1
    for (int layer = 0; layer < 4; layer++) {
        const int nch = (layer == 0) ? 2 : 4;
#pragma unroll
        for (int mt = 0; mt < 2; mt++)
#pragma unroll
            for (int nt = 0; nt < 8; nt++)
#pragma unroll
                for (int e = 0; e < 4; e++) acc[mt][nt][e] = 0.0f;

#pragma unroll 1
        for (int c = 0; c < nch; c++, g++) {
            asm volatile("cp.async.wait_group 0;" ::: "memory");
            __syncthreads();
            // safe to overwrite the other buffer: barrier proves all warps
            // finished reading chunk g-1 (and, at layer start, A is built)
            if (g + 1 < 14) issue_chunk(sb, tid, g + 1, (g + 1) & 1);

            const uint32_t wb = sb + WBUF_OFF + (g & 1) * WCHUNK;
#pragma unroll
            for (int kk = 0; kk < 4; kk++) {
                const uint32_t kByte = (uint32_t)(c * 64 + kk * 16) * 2;
                uint32_t ah[2][4], al[2][4];
#pragma unroll
                for (int mt = 0; mt < 2; mt++) {
                    const uint32_t aoff = aRowByte + (uint32_t)(mt * 16) * 528 + kByte;
                    ldsm4(ah[mt], sb + A_HI_OFF + aoff);
                    ldsm4(al[mt], sb + A_LO_OFF + aoff);
                }
#pragma unroll
                for (int ng = 0; ng < 4; ng++) {
                    const uint32_t bo = bRowByte + (uint32_t)(kk * 16) * 528
                                      + bColByte + (uint32_t)(ng * 16) * 2;
                    uint32_t w0, w1, w2, w3;
                    ldsm4t(w0, w1, w2, w3, wb + bo);
                    // pass 1: ah * w
                    mma16816h(acc[0][2 * ng],     ah[0], w0, w1);
                    mma16816h(acc[0][2 * ng + 1], ah[0], w2, w3);
                    mma16816h(acc[1][2 * ng],     ah[1], w0, w1);
                    mma16816h(acc[1][2 * ng + 1], ah[1], w2, w3);
                    // pass 2: al * w
                    mma16816h(acc[0][2 * ng],     al[0], w0, w1);
                    mma16816h(acc[0][2 * ng + 1], al[0], w2, w3);
                    mma16816h(acc[1][2 * ng],     al[1], w0, w1);
                    mma16816h(acc[1][2 * ng + 1], al[1], w2, w3);
                }
            }
        }

        __syncthreads();   // all warps done reading A before epilogue rewrites it
        const float* bl_bias = bias_s + layer * 256;
        if (layer < 3) {
            // epilogue: relu(D+b) -> fp16 hi/lo back into A (in place)
#pragma unroll
            for (int mt = 0; mt < 2; mt++) {
#pragma unroll
                for (int nt = 0; nt < 8; nt++) {
                    const int r0 = wm * 32 + mt * 16 + (lane >> 2);
                    const int c0 = wn * 64 + nt * 8 + (lane & 3) * 2;
                    const float bb0 = bl_bias[c0], bb1 = bl_bias[c0 + 1];
                    const float h00 = fmaxf(acc[mt][nt][0] + bb0, 0.0f);
                    const float h01 = fmaxf(acc[mt][nt][1] + bb1, 0.0f);
                    const float h10 = fmaxf(acc[mt][nt][2] + bb0, 0.0f);
                    const float h11 = fmaxf(acc[mt][nt][3] + bb1, 0.0f);
                    uint32_t hi, lo;
                    cvt2h(h00, h01, hi, lo);
                    *(uint32_t*)(smem + A_HI_OFF + (size_t)r0 * 528 + c0 * 2) = hi;
                    *(uint32_t*)(smem + A_LO_OFF + (size_t)r0 * 528 + c0 * 2) = lo;
                    cvt2h(h10, h11, hi, lo);
                    *(uint32_t*)(smem + A_HI_OFF + (size_t)(r0 + 8) * 528 + c0 * 2) = hi;
                    *(uint32_t*)(smem + A_LO_OFF + (size_t)(r0 + 8) * 528 + c0 * 2) = lo;
                }
            }
            // next phase's barrier orders these stores before the MMAs
        } else {
            // final: out = relu(D + b3) @ W4 + b4 (exact fp32)
            if (tid < 384) oacc[tid] = 0.0f;
            __syncthreads();
            float sres[4][3];
#pragma unroll
            for (int ii = 0; ii < 4; ii++)
#pragma unroll
                for (int o = 0; o < 3; o++) sres[ii][o] = 0.0f;
#pragma unroll
            for (int nt = 0; nt < 8; nt++) {
#pragma unroll
                for (int e = 0; e < 2; e++) {
                    const int col = wn * 64 + nt * 8 + (lane & 3) * 2 + e;
                    const float bb = bl_bias[col];
                    const float w40 = w4_s[col * 3 + 0];
                    const float w41 = w4_s[col * 3 + 1];
                    const float w42 = w4_s[col * 3 + 2];
                    const float h0 = fmaxf(acc[0][nt][e] + bb, 0.0f);
                    const float h1 = fmaxf(acc[0][nt][2 + e] + bb, 0.0f);
                    const float h2 = fmaxf(acc[1][nt][e] + bb, 0.0f);
                    const float h3 = fmaxf(acc[1][nt][2 + e] + bb, 0.0f);
                    sres[0][0] = fmaf(h0, w40, sres[0][0]); sres[0][1] = fmaf(h0, w41, sres[0][1]); sres[0][2] = fmaf(h0, w42, sres[0][2]);
                    sres[1][0] = fmaf(h1, w40, sres[1][0]); sres[1][1] = fmaf(h1, w41, sres[1][1]); sres[1][2] = fmaf(h1, w42, sres[1][2]);
                    sres[2][0] = fmaf(h2, w40, sres[2][0]); sres[2][1] = fmaf(h2, w41, sres[2][1]); sres[2][2] = fmaf(h2, w42, sres[2][2]);
                    sres[3][0] = fmaf(h3, w40, sres[3][0]); sres[3][1] = fmaf(h3, w41, sres[3][1]); sres[3][2] = fmaf(h3, w42, sres[3][2]);
                }
            }
            const int rbase = wm * 32 + (lane >> 2);
#pragma unroll
            for (int ii = 0; ii < 4; ii++) {
                const int row = rbase + ii * 8;
#pragma unroll
                for (int o = 0; o < 3; o++)
                    atomicAdd(&oacc[row * 3 + o], sres[ii][o]);
            }
            __syncthreads();
            if (tid < 128) {
                const size_t base = (size_t)(b * 3) * (HQv * WQv) + (size_t)yq * WQv + xq;
                out[base]                           = oacc[tid * 3 + 0] + b4_s[0];
                out[base + (size_t)(HQv * WQv)]     = oacc[tid * 3 + 1] + b4_s[1];
                out[base + (size_t)(2 * HQv * WQv)] = oacc[tid * 3 + 2] + b4_s[2];
            }
        }
    }
}

// ---------------------------------------------------------------------------
extern "C" void kernel_launch(void* const* d_in, const int* in_sizes, int n_in,
                              void* d_out, int out_size)
{
    const float* x     = (const float*)d_in[0];
    const float* coord = (const float*)d_in[1];
    const float* cell  = (const float*)d_in[2];
    const float* lr    = (const float*)d_in[3];
    const float* W0    = (const float*)d_in[4];
    const float* b0    = (const float*)d_in[5];
    const float* W1    = (const float*)d_in[6];
    const float* b1    = (const float*)d_in[7];
    const float* W2    = (const float*)d_in[8];
    const float* b2    = (const float*)d_in[9];
    const float* W3    = (const float*)d_in[10];
    const float* b3    = (const float*)d_in[11];
    const float* W4    = (const float*)d_in[12];
    const float* b4    = (const float*)d_in[13];
    float* out = (float*)d_out;

    liif_prep_kernel<<<896, 256>>>(W0, W1, W2, W3);

    const int P = out_size / 3;      // 589824
    const int nblk = P / MT;         // 4608

    cudaFuncSetAttribute(liif_hmma_kernel,
                         cudaFuncAttributeMaxDynamicSharedMemorySize, SMEM_TOTAL);
    liif_hmma_kernel<<<nblk, NTH, SMEM_TOTAL>>>(
        x, coord, cell, lr, b0, b1, b2, b3, W4, b4, out);
}

// round 8
// speedup vs baseline: 1.7357x; 1.1793x over previous
#include <cuda_runtime.h>
#include <cuda_fp16.h>
#include <cstdint>

// ============================================================================
// LIIF sampler, fp16 2-pass mma.sync. Round 8: per-N-group decoupled pipelines.
// 4 column-groups (64 cols each), each = 4 warps (one per SMSP) with a private
// W ring + named barrier; full __syncthreads only at layer boundaries.
// L0 K trimmed to 80. Final-layer reduction via shuffles (no atomics).
// ============================================================================

#define HQv 384
#define WQv 384
#define HFv 48
#define WFv 48

#define MT  128
#define NTH 512

// smem layout (bytes)
#define A_HI_OFF 0
#define A_LO_OFF 67584                   // 128*528
#define WRING_OFF 135168
#define GBUF  9216                       // 64 rows * 144B
#define GRING (2 * GBUF)                 // 18432 per group
#define BIAS_OFF (WRING_OFF + 4 * GRING) // 208896
#define W4_OFF   (BIAS_OFF + 4096)       // 212992
#define B4_OFF   (W4_OFF + 3072)         // 216064
#define OACC_OFF (B4_OFF + 16)           // 216080 : [4][128][3] fp32 = 6144
#define SMEM_TOTAL (OACC_OFF + 6144)     // 222224

// weight blob: per layer one fp16 plane [kpad][256]. kpad: L0=128, L1..3=256.
__device__ __align__(128) unsigned char g_wblob[458752];
__constant__ int c_lbase[4] = {0, 65536, 196608, 327680};

// ---------------------------------------------------------------------------
__device__ __forceinline__ uint32_t smem_u32(const void* p) {
    uint32_t a;
    asm("{ .reg .u64 t; cvta.to.shared.u64 t, %1; cvt.u32.u64 %0, t; }"
        : "=r"(a) : "l"(p));
    return a;
}
__device__ __forceinline__ void ldsm4(uint32_t* r, uint32_t a) {
    asm volatile("ldmatrix.sync.aligned.m8n8.x4.shared.b16 {%0,%1,%2,%3}, [%4];"
                 : "=r"(r[0]), "=r"(r[1]), "=r"(r[2]), "=r"(r[3]) : "r"(a));
}
__device__ __forceinline__ void ldsm4t(uint32_t& r0, uint32_t& r1, uint32_t& r2,
                                       uint32_t& r3, uint32_t a) {
    asm volatile("ldmatrix.sync.aligned.m8n8.x4.trans.shared.b16 {%0,%1,%2,%3}, [%4];"
                 : "=r"(r0), "=r"(r1), "=r"(r2), "=r"(r3) : "r"(a));
}
__device__ __forceinline__ void mma16816h(float* d, const uint32_t* a,
                                          uint32_t b0, uint32_t b1) {
    asm volatile(
        "mma.sync.aligned.m16n8k16.row.col.f32.f16.f16.f32 "
        "{%0,%1,%2,%3}, {%4,%5,%6,%7}, {%8,%9}, {%0,%1,%2,%3};"
        : "+f"(d[0]), "+f"(d[1]), "+f"(d[2]), "+f"(d[3])
        : "r"(a[0]), "r"(a[1]), "r"(a[2]), "r"(a[3]), "r"(b0), "r"(b1));
}
__device__ __forceinline__ void cpasync16(uint32_t dst, const void* src) {
    asm volatile("cp.async.cg.shared.global [%0], [%1], 16;"
                 :: "r"(dst), "l"(src) : "memory");
}
__device__ __forceinline__ void cp_commit() {
    asm volatile("cp.async.commit_group;" ::: "memory");
}
__device__ __forceinline__ void cvt2h(float a, float b, uint32_t& hi, uint32_t& lo) {
    __half ah = __float2half_rn(a), bh = __float2half_rn(b);
    __half al = __float2half_rn(a - __half2float(ah));
    __half bl = __float2half_rn(b - __half2float(bh));
    hi = (uint32_t)__half_as_ushort(ah) | ((uint32_t)__half_as_ushort(bh) << 16);
    lo = (uint32_t)__half_as_ushort(al) | ((uint32_t)__half_as_ushort(bl) << 16);
}

// global chunk index g (0..13) -> layer / local chunk. g==1 is the 16-row tail of L0.
__device__ __forceinline__ void chunk_of(int g, int& layer, int& c) {
    if (g < 2) { layer = 0; c = g; }
    else { layer = 1 + (g - 2) / 4; c = (g - 2) & 3; }
}

// stage this group's 64-col slice of chunk g into its ring buffer bsel
__device__ __forceinline__ void issue_group_chunk(uint32_t sb, int tid, int grp,
                                                  int g, int bsel) {
    int layer, c;
    chunk_of(g, layer, c);
    const int rows = (g == 1) ? 16 : 64;
    const unsigned char* src0 = g_wblob + c_lbase[layer]
                              + (size_t)c * 64 * 512 + (size_t)grp * 128;
    const int t = tid & 127;
#pragma unroll
    for (int it = 0; it < 4; it++) {
        const int i = t + it * 128;   // 0..511
        const int r = i >> 3, s = i & 7;
        if (r < rows)
            cpasync16(sb + WRING_OFF + grp * GRING + bsel * GBUF + r * 144 + s * 16,
                      src0 + (size_t)r * 512 + s * 16);
    }
    cp_commit();
}

// ---------------------------------------------------------------------------
// Prep: W0..W3 fp32 -> single fp16 plane each.
// ---------------------------------------------------------------------------
__global__ void liif_prep_kernel(const float* __restrict__ W0, const float* __restrict__ W1,
                                 const float* __restrict__ W2, const float* __restrict__ W3)
{
    const int row = blockIdx.x;
    const int n = threadIdx.x;
    int layer, k;
    if (row < 128) { layer = 0; k = row; }
    else { layer = 1 + (row - 128) / 256; k = (row - 128) & 255; }
    const float* W = (layer == 0) ? W0 : (layer == 1) ? W1 : (layer == 2) ? W2 : W3;
    const int Kl = (layer == 0) ? 71 : 256;
    const float val = (k < Kl) ? W[k * 256 + n] : 0.0f;
    *(unsigned short*)(g_wblob + c_lbase[layer] + (size_t)k * 512 + n * 2) =
        __half_as_ushort(__float2half_rn(val));
}

// ---------------------------------------------------------------------------
__global__ __launch_bounds__(NTH, 1)
void liif_hmma_kernel(
    const float* __restrict__ x, const float* __restrict__ coord,
    const float* __restrict__ cell, const float* __restrict__ lr,
    const float* __restrict__ b0, const float* __restrict__ b1,
    const float* __restrict__ b2, const float* __restrict__ b3,
    const float* __restrict__ W4, const float* __restrict__ b4,
    float* __restrict__ out)
{
    extern __shared__ __align__(16) char smem[];
    const uint32_t sb = smem_u32(smem);
    const int tid = threadIdx.x;
    const int lane = tid & 31;
    const int wid = tid >> 5;
    const int wm = wid & 3;     // 4 warps along M (32 rows each)
    const int grp = wid >> 2;   // column group 0..3 (64 cols each); 1 warp/SMSP/group

    float* bias_s = (float*)(smem + BIAS_OFF);
    float* w4_s   = (float*)(smem + W4_OFF);
    float* b4_s   = (float*)(smem + B4_OFF);
    float* oacc   = (float*)(smem + OACC_OFF);

    // prefetch this group's slice of chunk 0 (lands during gather)
    issue_group_chunk(sb, tid, grp, 0, 0);

    // stage biases + W4
    if (tid < 256) {
        bias_s[tid] = b0[tid]; bias_s[256 + tid] = b1[tid];
        bias_s[512 + tid] = b2[tid]; bias_s[768 + tid] = b3[tid];
    }
    for (int i = tid; i < 768; i += NTH) w4_s[i] = W4[i];
    if (tid < 3) b4_s[tid] = b4[tid];

    // ---- gather -> A0 (fp16 hi/lo, 128 point-rows, stride 528B) ----
    const int p  = tid & 127;
    const int q  = tid >> 7;   // 0..3
    const int gp = blockIdx.x * MT + p;
    const int b  = gp / (HQv * WQv);
    const int rem = gp % (HQv * WQv);
    const int yq = rem / WQv, xq = rem % WQv;
    const float gy = coord[((size_t)(b * HQv + yq) * WQv + xq) * 2 + 0];
    const float gx = coord[((size_t)(b * HQv + yq) * WQv + xq) * 2 + 1];

    float tx = __fmul_rn(__fadd_rn(__fmul_rn(__fadd_rn(gx, 1.0f), (float)WFv), -1.0f), 0.5f);
    float ty = __fmul_rn(__fadd_rn(__fmul_rn(__fadd_rn(gy, 1.0f), (float)HFv), -1.0f), 0.5f);
    const int ixn = (int)rintf(tx);
    const int iyn = (int)rintf(ty);
    const bool valid = (ixn >= 0) && (ixn < WFv) && (iyn >= 0) && (iyn < HFv);
    const int ixc = min(max(ixn, 0), WFv - 1);
    const int iyc = min(max(iyn, 0), HFv - 1);

    if (q < 2) {   // channels q*32 .. q*32+31
        const float* xb = x + (size_t)b * 64 * (HFv * WFv) + (size_t)iyc * WFv + ixc;
        char* rh = smem + A_HI_OFF + (size_t)p * 528 + q * 64;
        char* rl = smem + A_LO_OFF + (size_t)p * 528 + q * 64;
#pragma unroll
        for (int j = 0; j < 16; j++) {
            const int c0 = q * 32 + 2 * j;
            const float f0 = valid ? xb[(size_t)c0 * (HFv * WFv)] : 0.0f;
            const float f1 = valid ? xb[(size_t)(c0 + 1) * (HFv * WFv)] : 0.0f;
            uint32_t hi, lo;
            cvt2h(f0, f1, hi, lo);
            *(uint32_t*)(rh + j * 4) = hi;
            *(uint32_t*)(rl + j * 4) = lo;
        }
    } else if (q == 2) {  // scalar features -> cols 64..79 (+pad to 95)
        float qy = 0.0f, qx = 0.0f;
        if (valid) {
            qy = __fadd_rn(__fdiv_rn(__fadd_rn(__fmul_rn(2.0f, (float)iyc), 1.0f), (float)HFv), -1.0f);
            qx = __fadd_rn(__fdiv_rn(__fadd_rn(__fmul_rn(2.0f, (float)ixc), 1.0f), (float)WFv), -1.0f);
        }
        float vals[16];
#pragma unroll
        for (int i = 0; i < 16; i++) vals[i] = 0.0f;
        vals[0] = __fmul_rn(__fadd_rn(gy, -qy), (float)HFv);
        vals[1] = __fmul_rn(__fadd_rn(gx, -qx), (float)WFv);
        vals[2] = __fmul_rn(cell[b * 2 + 0], (float)HFv);
        vals[3] = __fmul_rn(cell[b * 2 + 1], (float)WFv);
        const float rx = 1.0f / (float)HFv, ry = 1.0f / (float)WFv;
        const float lo_c = -1.0f + 1e-6f, hi_c = 1.0f - 1e-6f;
        float s[3][4];
        int j = 0;
#pragma unroll
        for (int a = 0; a < 2; a++) {
#pragma unroll
            for (int c2 = 0; c2 < 2; c2++) {
                const float vx = a ? 1.0f : -1.0f;
                const float vy = c2 ? 1.0f : -1.0f;
                float cy = __fadd_rn(__fadd_rn(gy, __fmul_rn(vx, rx)), 1e-6f);
                float cx = __fadd_rn(__fadd_rn(gx, __fmul_rn(vy, ry)), 1e-6f);
                cy = fminf(fmaxf(cy, lo_c), hi_c);
                cx = fminf(fmaxf(cx, lo_c), hi_c);
                float fx = __fmul_rn(__fadd_rn(__fmul_rn(__fadd_rn(cx, 1.0f), (float)WFv), -1.0f), 0.5f);
                float fy = __fmul_rn(__fadd_rn(__fmul_rn(__fadd_rn(cy, 1.0f), (float)HFv), -1.0f), 0.5f);
                int jx = min(max((int)rintf(fx), 0), WFv - 1);
                int jy = min(max((int)rintf(fy), 0), HFv - 1);
#pragma unroll
                for (int ch = 0; ch < 3; ch++)
                    s[ch][j] = lr[((size_t)(b * 3 + ch) * HFv + jy) * WFv + jx];
                j++;
            }
        }
#pragma unroll
        for (int ch = 0; ch < 3; ch++) {
            const float m = 0.25f * (s[ch][0] + s[ch][1] + s[ch][2] + s[ch][3]);
            float v = 0.0f;
#pragma unroll
            for (int qq = 0; qq < 4; qq++) { const float d = s[ch][qq] - m; v += d * d; }
            vals[4 + ch] = sqrtf(v * (1.0f / 3.0f));
        }
        char* rh = smem + A_HI_OFF + (size_t)p * 528 + 128;
        char* rl = smem + A_LO_OFF + (size_t)p * 528 + 128;
#pragma unroll
        for (int k = 0; k < 8; k++) {   // cols 64..79 used (kpad=80)
            uint32_t hi, lo;
            cvt2h(vals[2 * k], vals[2 * k + 1], hi, lo);
            *(uint32_t*)(rh + k * 4) = hi;
            *(uint32_t*)(rl + k * 4) = lo;
        }
    }
    __syncthreads();

    // ---- 4 MMA layers, group-decoupled phases ----
    float acc[2][8][4];
    const uint32_t aRowByte = (uint32_t)(wm * 32 + (lane & 15)) * 528 + (lane >> 4) * 16;
    const uint32_t wRowByte = (uint32_t)(lane & 15) * 144;
    const uint32_t wColByte = (uint32_t)(lane >> 4) * 16;
    const uint32_t wbg = sb + WRING_OFF + grp * GRING;
    const uint32_t barid = 1 + grp;

    int g = 0;  // global chunk index (0..13)
#pragma unroll 1
    for (int layer = 0; layer < 4; layer++) {
        const int nch = (layer == 0) ? 2 : 4;
#pragma unroll
        for (int mt = 0; mt < 2; mt++)
#pragma unroll
            for (int nt = 0; nt < 8; nt++)
#pragma unroll
                for (int e = 0; e < 4; e++) acc[mt][nt][e] = 0.0f;

#pragma unroll 1
        for (int c = 0; c < nch; c++, g++) {
            asm volatile("cp.async.wait_group 0;" ::: "memory");
            asm volatile("bar.sync %0, 128;" :: "r"(barid) : "memory");
            if (g + 1 < 14) issue_group_chunk(sb, tid, grp, g + 1, (g + 1) & 1);

            const uint32_t wb = wbg + (g & 1) * GBUF;
            const int ks = (g == 1) ? 1 : 4;   // L0 tail chunk: 16 rows
#pragma unroll 1
            for (int kk = 0; kk < ks; kk++) {
                const uint32_t kByte = (uint32_t)(c * 64 + kk * 16) * 2;
                uint32_t ah[2][4], al[2][4];
#pragma unroll
                for (int mt = 0; mt < 2; mt++) {
                    const uint32_t aoff = aRowByte + (uint32_t)(mt * 16) * 528 + kByte;
                    ldsm4(ah[mt], sb + A_HI_OFF + aoff);
                    ldsm4(al[mt], sb + A_LO_OFF + aoff);
                }
#pragma unroll
                for (int ng = 0; ng < 4; ng++) {
                    const uint32_t bo = wRowByte + (uint32_t)(kk * 16) * 144
                                      + wColByte + (uint32_t)ng * 32;
                    uint32_t w0, w1, w2, w3;
                    ldsm4t(w0, w1, w2, w3, wb + bo);
                    mma16816h(acc[0][2 * ng],     ah[0], w0, w1);
                    mma16816h(acc[0][2 * ng + 1], ah[0], w2, w3);
                    mma16816h(acc[1][2 * ng],     ah[1], w0, w1);
                    mma16816h(acc[1][2 * ng + 1], ah[1], w2, w3);
                    mma16816h(acc[0][2 * ng],     al[0], w0, w1);
                    mma16816h(acc[0][2 * ng + 1], al[0], w2, w3);
                    mma16816h(acc[1][2 * ng],     al[1], w0, w1);
                    mma16816h(acc[1][2 * ng + 1], al[1], w2, w3);
                }
            }
        }

        __syncthreads();   // all groups done reading A
        const float* bl_bias = bias_s + layer * 256;
        if (layer < 3) {
            // epilogue: relu(D+b) -> fp16 hi/lo back into A (in place)
#pragma unroll
            for (int mt = 0; mt < 2; mt++) {
#pragma unroll
                for (int nt = 0; nt < 8; nt++) {
                    const int r0 = wm * 32 + mt * 16 + (lane >> 2);
                    const int c0 = grp * 64 + nt * 8 + (lane & 3) * 2;
                    const float bb0 = bl_bias[c0], bb1 = bl_bias[c0 + 1];
                    const float h00 = fmaxf(acc[mt][nt][0] + bb0, 0.0f);
                    const float h01 = fmaxf(acc[mt][nt][1] + bb1, 0.0f);
                    const float h10 = fmaxf(acc[mt][nt][2] + bb0, 0.0f);
                    const float h11 = fmaxf(acc[mt][nt][3] + bb1, 0.0f);
                    uint32_t hi, lo;
                    cvt2h(h00, h01, hi, lo);
                    *(uint32_t*)(smem + A_HI_OFF + (size_t)r0 * 528 + c0 * 2) = hi;
                    *(uint32_t*)(smem + A_LO_OFF + (size_t)r0 * 528 + c0 * 2) = lo;
                    cvt2h(h10, h11, hi, lo);
                    *(uint32_t*)(smem + A_HI_OFF + (size_t)(r0 + 8) * 528 + c0 * 2) = hi;
                    *(uint32_t*)(smem + A_LO_OFF + (size_t)(r0 + 8) * 528 + c0 * 2) = lo;
                }
            }
            __syncthreads();   // A ready for next layer (all groups)
        } else {
            // final: out = relu(D + b3) @ W4 + b4, reduced via shuffles + smem
            float sres[4][3];
#pragma unroll
            for (int ii = 0; ii < 4; ii++)
#pragma unroll
                for (int o = 0; o < 3; o++) sres[ii][o] = 0.0f;
#pragma unroll
            for (int nt = 0; nt < 8; nt++) {
#pragma unroll
                for (int e = 0; e < 2; e++) {
                    const int col = grp * 64 + nt * 8 + (lane & 3) * 2 + e;
                    const float bb = bl_bias[col];
                    const float w40 = w4_s[col * 3 + 0];
                    const float w41 = w4_s[col * 3 + 1];
                    const float w42 = w4_s[col * 3 + 2];
                    const float h0 = fmaxf(acc[0][nt][e] + bb, 0.0f);
                    const float h1 = fmaxf(acc[0][nt][2 + e] + bb, 0.0f);
                    const float h2 = fmaxf(acc[1][nt][e] + bb, 0.0f);
                    const float h3 = fmaxf(acc[1][nt][2 + e] + bb, 0.0f);
                    sres[0][0] = fmaf(h0, w40, sres[0][0]); sres[0][1] = fmaf(h0, w41, sres[0][1]); sres[0][2] = fmaf(h0, w42, sres[0][2]);
                    sres[1][0] = fmaf(h1, w40, sres[1][0]); sres[1][1] = fmaf(h1, w41, sres[1][1]); sres[1][2] = fmaf(h1, w42, sres[1][2]);
                    sres[2][0] = fmaf(h2, w40, sres[2][0]); sres[2][1] = fmaf(h2, w41, sres[2][1]); sres[2][2] = fmaf(h2, w42, sres[2][2]);
                    sres[3][0] = fmaf(h3, w40, sres[3][0]); sres[3][1] = fmaf(h3, w41, sres[3][1]); sres[3][2] = fmaf(h3, w42, sres[3][2]);
                }
            }
            // quad-reduce over lane&3 (the 4 col-subsets of this warp)
#pragma unroll
            for (int ii = 0; ii < 4; ii++)
#pragma unroll
                for (int o = 0; o < 3; o++) {
                    float v = sres[ii][o];
                    v += __shfl_xor_sync(0xffffffff, v, 1);
                    v += __shfl_xor_sync(0xffffffff, v, 2);
                    sres[ii][o] = v;
                }
            if ((lane & 3) == 0) {
                const int rbase = wm * 32 + (lane >> 2);
#pragma unroll
                for (int ii = 0; ii < 4; ii++) {
                    const int row = rbase + ii * 8;
#pragma unroll
                    for (int o = 0; o < 3; o++)
                        oacc[(grp * 128 + row) * 3 + o] = sres[ii][o];
                }
            }
            __syncthreads();
            if (tid < 128) {
                const float o0 = oacc[tid * 3] + oacc[(128 + tid) * 3]
                               + oacc[(256 + tid) * 3] + oacc[(384 + tid) * 3] + b4_s[0];
                const float o1 = oacc[tid * 3 + 1] + oacc[(128 + tid) * 3 + 1]
                               + oacc[(256 + tid) * 3 + 1] + oacc[(384 + tid) * 3 + 1] + b4_s[1];
                const float o2 = oacc[tid * 3 + 2] + oacc[(128 + tid) * 3 + 2]
                               + oacc[(256 + tid) * 3 + 2] + oacc[(384 + tid) * 3 + 2] + b4_s[2];
                const size_t base = (size_t)(b * 3) * (HQv * WQv) + (size_t)yq * WQv + xq;
                out[base]                           = o0;
                out[base + (size_t)(HQv * WQv)]     = o1;
                out[base + (size_t)(2 * HQv * WQv)] = o2;
            }
        }
    }
}

// ---------------------------------------------------------------------------
extern "C" void kernel_launch(void* const* d_in, const int* in_sizes, int n_in,
                              void* d_out, int out_size)
{
    const float* x     = (const float*)d_in[0];
    const float* coord = (const float*)d_in[1];
    const float* cell  = (const float*)d_in[2];
    const float* lr    = (const float*)d_in[3];
    const float* W0    = (const float*)d_in[4];
    const float* b0    = (const float*)d_in[5];
    const float* W1    = (const float*)d_in[6];
    const float* b1    = (const float*)d_in[7];
    const float* W2    = (const float*)d_in[8];
    const float* b2    = (const float*)d_in[9];
    const float* W3    = (const float*)d_in[10];
    const float* b3    = (const float*)d_in[11];
    const float* W4    = (const float*)d_in[12];
    const float* b4    = (const float*)d_in[13];
    float* out = (float*)d_out;

    liif_prep_kernel<<<896, 256>>>(W0, W1, W2, W3);

    const int P = out_size / 3;      // 589824
    const int nblk = P / MT;         // 4608

    cudaFuncSetAttribute(liif_hmma_kernel,
                         cudaFuncAttributeMaxDynamicSharedMemorySize, SMEM_TOTAL);
    liif_hmma_kernel<<<nblk, NTH, SMEM_TOTAL>>>(
        x, coord, cell, lr, b0, b1, b2, b3, W4, b4, out);
}

// round 9
// speedup vs baseline: 2.9370x; 1.6921x over previous
#include <cuda_runtime.h>
#include <cuda_fp16.h>
#include <cstdint>

// ============================================================================
// LIIF sampler, single-pass fp16 mma.sync (A fp16, W fp16, fp32 accum).
// Round 9: per-N-group decoupled pipelines (R8) + 3-deep W ring with
// wait_group 1, single A plane. Final 256->3 layer exact fp32.
// ============================================================================

#define HQv 384
#define WQv 384
#define HFv 48
#define WFv 48

#define MT  128
#define NTH 512

// smem layout (bytes)
#define A_OFF 0                            // 128*528 = 67584
#define WRING_OFF 67584
#define GBUF  9216                         // 64 rows * 144B
#define GRING (3 * GBUF)                   // 27648 per group (3-deep)
#define BIAS_OFF (WRING_OFF + 4 * GRING)   // 178176
#define W4_OFF   (BIAS_OFF + 4096)         // 182272
#define B4_OFF   (W4_OFF + 3072)           // 185344
#define OACC_OFF (B4_OFF + 16)             // 185360 : [4][128][3] fp32
#define SMEM_TOTAL (OACC_OFF + 6144)       // 191504

// weight blob: per layer one fp16 plane [kpad][256]. kpad: L0=128, L1..3=256.
__device__ __align__(128) unsigned char g_wblob[458752];
__constant__ int c_lbase[4] = {0, 65536, 196608, 327680};

// ---------------------------------------------------------------------------
__device__ __forceinline__ uint32_t smem_u32(const void* p) {
    uint32_t a;
    asm("{ .reg .u64 t; cvta.to.shared.u64 t, %1; cvt.u32.u64 %0, t; }"
        : "=r"(a) : "l"(p));
    return a;
}
__device__ __forceinline__ void ldsm4(uint32_t* r, uint32_t a) {
    asm volatile("ldmatrix.sync.aligned.m8n8.x4.shared.b16 {%0,%1,%2,%3}, [%4];"
                 : "=r"(r[0]), "=r"(r[1]), "=r"(r[2]), "=r"(r[3]) : "r"(a));
}
__device__ __forceinline__ void ldsm4t(uint32_t& r0, uint32_t& r1, uint32_t& r2,
                                       uint32_t& r3, uint32_t a) {
    asm volatile("ldmatrix.sync.aligned.m8n8.x4.trans.shared.b16 {%0,%1,%2,%3}, [%4];"
                 : "=r"(r0), "=r"(r1), "=r"(r2), "=r"(r3) : "r"(a));
}
__device__ __forceinline__ void mma16816h(float* d, const uint32_t* a,
                                          uint32_t b0, uint32_t b1) {
    asm volatile(
        "mma.sync.aligned.m16n8k16.row.col.f32.f16.f16.f32 "
        "{%0,%1,%2,%3}, {%4,%5,%6,%7}, {%8,%9}, {%0,%1,%2,%3};"
        : "+f"(d[0]), "+f"(d[1]), "+f"(d[2]), "+f"(d[3])
        : "r"(a[0]), "r"(a[1]), "r"(a[2]), "r"(a[3]), "r"(b0), "r"(b1));
}
__device__ __forceinline__ void cpasync16(uint32_t dst, const void* src) {
    asm volatile("cp.async.cg.shared.global [%0], [%1], 16;"
                 :: "r"(dst), "l"(src) : "memory");
}
__device__ __forceinline__ void cp_commit() {
    asm volatile("cp.async.commit_group;" ::: "memory");
}
__device__ __forceinline__ uint32_t cvt1h(float a, float b) {
    __half ah = __float2half_rn(a), bh = __float2half_rn(b);
    return (uint32_t)__half_as_ushort(ah) | ((uint32_t)__half_as_ushort(bh) << 16);
}

// global chunk index g (0..13): g==1 is the 16-row tail of L0 (kpad 80).
__device__ __forceinline__ void chunk_of(int g, int& layer, int& c) {
    if (g < 2) { layer = 0; c = g; }
    else { layer = 1 + (g - 2) / 4; c = (g - 2) & 3; }
}

// stage this group's 64-col slice of chunk g into ring buffer (g % 3)
__device__ __forceinline__ void issue_group_chunk(uint32_t sb, int tid, int grp, int g) {
    int layer, c;
    chunk_of(g, layer, c);
    const int rows = (g == 1) ? 16 : 64;
    const int bsel = g % 3;
    const unsigned char* src0 = g_wblob + c_lbase[layer]
                              + (size_t)c * 64 * 512 + (size_t)grp * 128;
    const int t = tid & 127;
#pragma unroll
    for (int it = 0; it < 4; it++) {
        const int i = t + it * 128;   // 0..511
        const int r = i >> 3, s = i & 7;
        if (r < rows)
            cpasync16(sb + WRING_OFF + grp * GRING + bsel * GBUF + r * 144 + s * 16,
                      src0 + (size_t)r * 512 + s * 16);
    }
    cp_commit();
}

// ---------------------------------------------------------------------------
// Prep: W0..W3 fp32 -> single fp16 plane each.
// ---------------------------------------------------------------------------
__global__ void liif_prep_kernel(const float* __restrict__ W0, const float* __restrict__ W1,
                                 const float* __restrict__ W2, const float* __restrict__ W3)
{
    const int row = blockIdx.x;
    const int n = threadIdx.x;
    int layer, k;
    if (row < 128) { layer = 0; k = row; }
    else { layer = 1 + (row - 128) / 256; k = (row - 128) & 255; }
    const float* W = (layer == 0) ? W0 : (layer == 1) ? W1 : (layer == 2) ? W2 : W3;
    const int Kl = (layer == 0) ? 71 : 256;
    const float val = (k < Kl) ? W[k * 256 + n] : 0.0f;
    *(unsigned short*)(g_wblob + c_lbase[layer] + (size_t)k * 512 + n * 2) =
        __half_as_ushort(__float2half_rn(val));
}

// ---------------------------------------------------------------------------
__global__ __launch_bounds__(NTH, 1)
void liif_hmma_kernel(
    const float* __restrict__ x, const float* __restrict__ coord,
    const float* __restrict__ cell, const float* __restrict__ lr,
    const float* __restrict__ b0, const float* __restrict__ b1,
    const float* __restrict__ b2, const float* __restrict__ b3,
    const float* __restrict__ W4, const float* __restrict__ b4,
    float* __restrict__ out)
{
    extern __shared__ __align__(16) char smem[];
    const uint32_t sb = smem_u32(smem);
    const int tid = threadIdx.x;
    const int lane = tid & 31;
    const int wid = tid >> 5;
    const int wm = wid & 3;     // 4 warps along M (32 rows each)
    const int grp = wid >> 2;   // column group 0..3 (64 cols); 1 warp/SMSP/group

    float* bias_s = (float*)(smem + BIAS_OFF);
    float* w4_s   = (float*)(smem + W4_OFF);
    float* b4_s   = (float*)(smem + B4_OFF);
    float* oacc   = (float*)(smem + OACC_OFF);

    // prefetch this group's slices of chunks 0 and 1 (land during gather)
    issue_group_chunk(sb, tid, grp, 0);
    issue_group_chunk(sb, tid, grp, 1);

    // stage biases + W4
    if (tid < 256) {
        bias_s[tid] = b0[tid]; bias_s[256 + tid] = b1[tid];
        bias_s[512 + tid] = b2[tid]; bias_s[768 + tid] = b3[tid];
    }
    for (int i = tid; i < 768; i += NTH) w4_s[i] = W4[i];
    if (tid < 3) b4_s[tid] = b4[tid];

    // ---- gather -> A0 (fp16, 128 point-rows, stride 528B) ----
    const int p  = tid & 127;
    const int q  = tid >> 7;   // 0..3
    const int gp = blockIdx.x * MT + p;
    const int b  = gp / (HQv * WQv);
    const int rem = gp % (HQv * WQv);
    const int yq = rem / WQv, xq = rem % WQv;
    const float gy = coord[((size_t)(b * HQv + yq) * WQv + xq) * 2 + 0];
    const float gx = coord[((size_t)(b * HQv + yq) * WQv + xq) * 2 + 1];

    float tx = __fmul_rn(__fadd_rn(__fmul_rn(__fadd_rn(gx, 1.0f), (float)WFv), -1.0f), 0.5f);
    float ty = __fmul_rn(__fadd_rn(__fmul_rn(__fadd_rn(gy, 1.0f), (float)HFv), -1.0f), 0.5f);
    const int ixn = (int)rintf(tx);
    const int iyn = (int)rintf(ty);
    const bool valid = (ixn >= 0) && (ixn < WFv) && (iyn >= 0) && (iyn < HFv);
    const int ixc = min(max(ixn, 0), WFv - 1);
    const int iyc = min(max(iyn, 0), HFv - 1);

    if (q < 2) {   // channels q*32 .. q*32+31
        const float* xb = x + (size_t)b * 64 * (HFv * WFv) + (size_t)iyc * WFv + ixc;
        char* rh = smem + A_OFF + (size_t)p * 528 + q * 64;
#pragma unroll
        for (int j = 0; j < 16; j++) {
            const int c0 = q * 32 + 2 * j;
            const float f0 = valid ? xb[(size_t)c0 * (HFv * WFv)] : 0.0f;
            const float f1 = valid ? xb[(size_t)(c0 + 1) * (HFv * WFv)] : 0.0f;
            *(uint32_t*)(rh + j * 4) = cvt1h(f0, f1);
        }
    } else if (q == 2) {  // scalar features -> cols 64..79 (kpad=80)
        float qy = 0.0f, qx = 0.0f;
        if (valid) {
            qy = __fadd_rn(__fdiv_rn(__fadd_rn(__fmul_rn(2.0f, (float)iyc), 1.0f), (float)HFv), -1.0f);
            qx = __fadd_rn(__fdiv_rn(__fadd_rn(__fmul_rn(2.0f, (float)ixc), 1.0f), (float)WFv), -1.0f);
        }
        float vals[16];
#pragma unroll
        for (int i = 0; i < 16; i++) vals[i] = 0.0f;
        vals[0] = __fmul_rn(__fadd_rn(gy, -qy), (float)HFv);
        vals[1] = __fmul_rn(__fadd_rn(gx, -qx), (float)WFv);
        vals[2] = __fmul_rn(cell[b * 2 + 0], (float)HFv);
        vals[3] = __fmul_rn(cell[b * 2 + 1], (float)WFv);
        const float rx = 1.0f / (float)HFv, ry = 1.0f / (float)WFv;
        const float lo_c = -1.0f + 1e-6f, hi_c = 1.0f - 1e-6f;
        float s[3][4];
        int j = 0;
#pragma unroll
        for (int a = 0; a < 2; a++) {
#pragma unroll
            for (int c2 = 0; c2 < 2; c2++) {
                const float vx = a ? 1.0f : -1.0f;
                const float vy = c2 ? 1.0f : -1.0f;
                float cy = __fadd_rn(__fadd_rn(gy, __fmul_rn(vx, rx)), 1e-6f);
                float cx = __fadd_rn(__fadd_rn(gx, __fmul_rn(vy, ry)), 1e-6f);
                cy = fminf(fmaxf(cy, lo_c), hi_c);
                cx = fminf(fmaxf(cx, lo_c), hi_c);
                float fx = __fmul_rn(__fadd_rn(__fmul_rn(__fadd_rn(cx, 1.0f), (float)WFv), -1.0f), 0.5f);
                float fy = __fmul_rn(__fadd_rn(__fmul_rn(__fadd_rn(cy, 1.0f), (float)HFv), -1.0f), 0.5f);
                int jx = min(max((int)rintf(fx), 0), WFv - 1);
                int jy = min(max((int)rintf(fy), 0), HFv - 1);
#pragma unroll
                for (int ch = 0; ch < 3; ch++)
                    s[ch][j] = lr[((size_t)(b * 3 + ch) * HFv + jy) * WFv + jx];
                j++;
            }
        }
#pragma unroll
        for (int ch = 0; ch < 3; ch++) {
            const float m = 0.25f * (s[ch][0] + s[ch][1] + s[ch][2] + s[ch][3]);
            float v = 0.0f;
#pragma unroll
            for (int qq = 0; qq < 4; qq++) { const float d = s[ch][qq] - m; v += d * d; }
            vals[4 + ch] = sqrtf(v * (1.0f / 3.0f));
        }
        char* rh = smem + A_OFF + (size_t)p * 528 + 128;
#pragma unroll
        for (int k = 0; k < 8; k++)
            *(uint32_t*)(rh + k * 4) = cvt1h(vals[2 * k], vals[2 * k + 1]);
    }
    __syncthreads();

    // ---- 4 MMA layers, group-decoupled phases, 3-deep W ring ----
    float acc[2][8][4];
    const uint32_t aRowByte = (uint32_t)(wm * 32 + (lane & 15)) * 528 + (lane >> 4) * 16;
    const uint32_t wRowByte = (uint32_t)(lane & 15) * 144;
    const uint32_t wColByte = (uint32_t)(lane >> 4) * 16;
    const uint32_t wbg = sb + WRING_OFF + grp * GRING;
    const uint32_t barid = 1 + grp;

    int g = 0;  // global chunk index (0..13)
#pragma unroll 1
    for (int layer = 0; layer < 4; layer++) {
        const int nch = (layer == 0) ? 2 : 4;
#pragma unroll
        for (int mt = 0; mt < 2; mt++)
#pragma unroll
            for (int nt = 0; nt < 8; nt++)
#pragma unroll
                for (int e = 0; e < 4; e++) acc[mt][nt][e] = 0.0f;

#pragma unroll 1
        for (int c = 0; c < nch; c++, g++) {
            if (g < 13) asm volatile("cp.async.wait_group 1;" ::: "memory");
            else        asm volatile("cp.async.wait_group 0;" ::: "memory");
            asm volatile("bar.sync %0, 128;" :: "r"(barid) : "memory");
            if (g + 2 < 14) issue_group_chunk(sb, tid, grp, g + 2);

            const uint32_t wb = wbg + (g % 3) * GBUF;
            const int ks = (g == 1) ? 1 : 4;   // L0 tail chunk: 16 rows
#pragma unroll 1
            for (int kk = 0; kk < ks; kk++) {
                const uint32_t kByte = (uint32_t)(c * 64 + kk * 16) * 2;
                uint32_t ah[2][4];
#pragma unroll
                for (int mt = 0; mt < 2; mt++)
                    ldsm4(ah[mt], sb + A_OFF + aRowByte + (uint32_t)(mt * 16) * 528 + kByte);
#pragma unroll
                for (int ng = 0; ng < 4; ng++) {
                    const uint32_t bo = wRowByte + (uint32_t)(kk * 16) * 144
                                      + wColByte + (uint32_t)ng * 32;
                    uint32_t w0, w1, w2, w3;
                    ldsm4t(w0, w1, w2, w3, wb + bo);
                    mma16816h(acc[0][2 * ng],     ah[0], w0, w1);
                    mma16816h(acc[0][2 * ng + 1], ah[0], w2, w3);
                    mma16816h(acc[1][2 * ng],     ah[1], w0, w1);
                    mma16816h(acc[1][2 * ng + 1], ah[1], w2, w3);
                }
            }
        }

        __syncthreads();   // all groups done reading A
        const float* bl_bias = bias_s + layer * 256;
        if (layer < 3) {
            // epilogue: relu(D+b) -> fp16 back into A (in place)
#pragma unroll
            for (int mt = 0; mt < 2; mt++) {
#pragma unroll
                for (int nt = 0; nt < 8; nt++) {
                    const int r0 = wm * 32 + mt * 16 + (lane >> 2);
                    const int c0 = grp * 64 + nt * 8 + (lane & 3) * 2;
                    const float bb0 = bl_bias[c0], bb1 = bl_bias[c0 + 1];
                    const float h00 = fmaxf(acc[mt][nt][0] + bb0, 0.0f);
                    const float h01 = fmaxf(acc[mt][nt][1] + bb1, 0.0f);
                    const float h10 = fmaxf(acc[mt][nt][2] + bb0, 0.0f);
                    const float h11 = fmaxf(acc[mt][nt][3] + bb1, 0.0f);
                    *(uint32_t*)(smem + A_OFF + (size_t)r0 * 528 + c0 * 2) = cvt1h(h00, h01);
                    *(uint32_t*)(smem + A_OFF + (size_t)(r0 + 8) * 528 + c0 * 2) = cvt1h(h10, h11);
                }
            }
            __syncthreads();   // A ready for next layer (all groups)
        } else {
            // final: out = relu(D + b3) @ W4 + b4, shuffle + smem reduction
            float sres[4][3];
#pragma unroll
            for (int ii = 0; ii < 4; ii++)
#pragma unroll
                for (int o = 0; o < 3; o++) sres[ii][o] = 0.0f;
#pragma unroll
            for (int nt = 0; nt < 8; nt++) {
#pragma unroll
                for (int e = 0; e < 2; e++) {
                    const int col = grp * 64 + nt * 8 + (lane & 3) * 2 + e;
                    const float bb = bl_bias[col];
                    const float w40 = w4_s[col * 3 + 0];
                    const float w41 = w4_s[col * 3 + 1];
                    const float w42 = w4_s[col * 3 + 2];
                    const float h0 = fmaxf(acc[0][nt][e] + bb, 0.0f);
                    const float h1 = fmaxf(acc[0][nt][2 + e] + bb, 0.0f);
                    const float h2 = fmaxf(acc[1][nt][e] + bb, 0.0f);
                    const float h3 = fmaxf(acc[1][nt][2 + e] + bb, 0.0f);
                    sres[0][0] = fmaf(h0, w40, sres[0][0]); sres[0][1] = fmaf(h0, w41, sres[0][1]); sres[0][2] = fmaf(h0, w42, sres[0][2]);
                    sres[1][0] = fmaf(h1, w40, sres[1][0]); sres[1][1] = fmaf(h1, w41, sres[1][1]); sres[1][2] = fmaf(h1, w42, sres[1][2]);
                    sres[2][0] = fmaf(h2, w40, sres[2][0]); sres[2][1] = fmaf(h2, w41, sres[2][1]); sres[2][2] = fmaf(h2, w42, sres[2][2]);
                    sres[3][0] = fmaf(h3, w40, sres[3][0]); sres[3][1] = fmaf(h3, w41, sres[3][1]); sres[3][2] = fmaf(h3, w42, sres[3][2]);
                }
            }
#pragma unroll
            for (int ii = 0; ii < 4; ii++)
#pragma unroll
                for (int o = 0; o < 3; o++) {
                    float v = sres[ii][o];
                    v += __shfl_xor_sync(0xffffffff, v, 1);
                    v += __shfl_xor_sync(0xffffffff, v, 2);
                    sres[ii][o] = v;
                }
            if ((lane & 3) == 0) {
                const int rbase = wm * 32 + (lane >> 2);
#pragma unroll
                for (int ii = 0; ii < 4; ii++) {
                    const int row = rbase + ii * 8;
#pragma unroll
                    for (int o = 0; o < 3; o++)
                        oacc[(grp * 128 + row) * 3 + o] = sres[ii][o];
                }
            }
            __syncthreads();
            if (tid < 128) {
                const float o0 = oacc[tid * 3] + oacc[(128 + tid) * 3]
                               + oacc[(256 + tid) * 3] + oacc[(384 + tid) * 3] + b4_s[0];
                const float o1 = oacc[tid * 3 + 1] + oacc[(128 + tid) * 3 + 1]
                               + oacc[(256 + tid) * 3 + 1] + oacc[(384 + tid) * 3 + 1] + b4_s[1];
                const float o2 = oacc[tid * 3 + 2] + oacc[(128 + tid) * 3 + 2]
                               + oacc[(256 + tid) * 3 + 2] + oacc[(384 + tid) * 3 + 2] + b4_s[2];
                const size_t base = (size_t)(b * 3) * (HQv * WQv) + (size_t)yq * WQv + xq;
                out[base]                           = o0;
                out[base + (size_t)(HQv * WQv)]     = o1;
                out[base + (size_t)(2 * HQv * WQv)] = o2;
            }
        }
    }
}

// ---------------------------------------------------------------------------
extern "C" void kernel_launch(void* const* d_in, const int* in_sizes, int n_in,
                              void* d_out, int out_size)
{
    const float* x     = (const float*)d_in[0];
    const float* coord = (const float*)d_in[1];
    const float* cell  = (const float*)d_in[2];
    const float* lr    = (const float*)d_in[3];
    const float* W0    = (const float*)d_in[4];
    const float* b0    = (const float*)d_in[5];
    const float* W1    = (const float*)d_in[6];
    const float* b1    = (const float*)d_in[7];
    const float* W2    = (const float*)d_in[8];
    const float* b2    = (const float*)d_in[9];
    const float* W3    = (const float*)d_in[10];
    const float* b3    = (const float*)d_in[11];
    const float* W4    = (const float*)d_in[12];
    const float* b4    = (const float*)d_in[13];
    float* out = (float*)d_out;

    liif_prep_kernel<<<896, 256>>>(W0, W1, W2, W3);

    const int P = out_size / 3;      // 589824
    const int nblk = P / MT;         // 4608

    cudaFuncSetAttribute(liif_hmma_kernel,
                         cudaFuncAttributeMaxDynamicSharedMemorySize, SMEM_TOTAL);
    liif_hmma_kernel<<<nblk, NTH, SMEM_TOTAL>>>(
        x, coord, cell, lr, b0, b1, b2, b3, W4, b4, out);
}